// round 13
// baseline (speedup 1.0000x reference)
#include <cuda_runtime.h>
#include <cuda_fp16.h>
#include <cuda_bf16.h>
#include <cstdint>

#define N_NODES 50000
#define N_EDGES 600000
#define N_GRAPHS 64
#define HID 128
#define SCAN_NB ((N_NODES + 255) / 256)   // 196

__device__ __forceinline__ unsigned int h2_as_u32(__half2 h) {
    return *reinterpret_cast<unsigned int*>(&h);
}
__device__ __forceinline__ __half2 u32_as_h2(unsigned int u) {
    return *reinterpret_cast<__half2*>(&u);
}
__device__ __forceinline__ uint32_t smem_u32(const void* p) {
    uint32_t a;
    asm("{ .reg .u64 t; cvta.to.shared.u64 t, %1; cvt.u32.u64 %0, t; }" : "=r"(a) : "l"(p));
    return a;
}

// ---------------- scratch (static device globals; no allocation) ----------------
__device__ int    g_indeg[N_NODES];
__device__ float  g_dis[N_NODES];
__device__ int    g_offs[N_NODES + 1];
__device__ int    g_fill[N_NODES];
__device__ int    g_srcs[N_EDGES];
__device__ int    g_bsum[256];
__device__ __half g_h1h[(size_t)N_NODES * HID];  // ping buffer (layer1/layer3 out)
__device__ __half g_h2h[(size_t)N_NODES * HID];  // pong buffer (layer2 out)
__device__ int    g_gstart[N_GRAPHS + 1];

__device__ __forceinline__ int real_off(int i) { return g_offs[i] + g_bsum[i >> 8]; }

// ---------------- graph preprocessing ----------------
__global__ void k_init() {
    for (int i = blockIdx.x * blockDim.x + threadIdx.x; i < N_NODES;
         i += gridDim.x * blockDim.x) {
        g_indeg[i] = 0;
        g_fill[i] = 0;
    }
}

__global__ void k_degree(const int* __restrict__ ei) {
    int i = blockIdx.x * blockDim.x + threadIdx.x;
    if (i >= N_EDGES) return;
    int d = ei[N_EDGES + i];
    if (d >= 0 && d < N_NODES) atomicAdd(&g_indeg[d], 1);
}

__global__ void k_scan1(const int* __restrict__ batch) {
    __shared__ int wsum[8];
    int tid = threadIdx.x, lane = tid & 31, wid = tid >> 5;
    int i = blockIdx.x * 256 + tid;
    int v = (i < N_NODES) ? g_indeg[i] : 0;
    if (i < N_NODES) g_dis[i] = rsqrtf((float)(v + 1));
    int s = v;
    #pragma unroll
    for (int o = 1; o < 32; o <<= 1) {
        int t = __shfl_up_sync(0xffffffffu, s, o);
        if (lane >= o) s += t;
    }
    if (lane == 31) wsum[wid] = s;
    __syncthreads();
    if (tid == 0) {
        int run = 0;
        #pragma unroll
        for (int j = 0; j < 8; j++) { int t = wsum[j]; wsum[j] = run; run += t; }
        g_bsum[blockIdx.x] = run;
    }
    __syncthreads();
    int excl = wsum[wid] + (s - v);
    if (i <= N_NODES) g_offs[i] = excl;

    if (i < N_NODES) {
        int b = batch[i];
        if (b < 0) b = 0;
        if (b >= N_GRAPHS) b = N_GRAPHS - 1;
        int prev;
        if (i == 0) prev = -1;
        else {
            prev = batch[i - 1];
            if (prev < 0) prev = 0;
            if (prev >= N_GRAPHS) prev = N_GRAPHS - 1;
        }
        for (int g = prev + 1; g <= b; g++) g_gstart[g] = i;
        if (i == N_NODES - 1)
            for (int g = b + 1; g <= N_GRAPHS; g++) g_gstart[g] = N_NODES;
    }
}

__global__ void k_scan2() {
    __shared__ int wsum[8];
    int tid = threadIdx.x, lane = tid & 31, wid = tid >> 5;
    int v = (tid < SCAN_NB) ? g_bsum[tid] : 0;
    int s = v;
    #pragma unroll
    for (int o = 1; o < 32; o <<= 1) {
        int t = __shfl_up_sync(0xffffffffu, s, o);
        if (lane >= o) s += t;
    }
    if (lane == 31) wsum[wid] = s;
    __syncthreads();
    if (tid == 0) {
        int run = 0;
        #pragma unroll
        for (int j = 0; j < 8; j++) { int t = wsum[j]; wsum[j] = run; run += t; }
    }
    __syncthreads();
    int excl = wsum[wid] + (s - v);
    if (tid < SCAN_NB) g_bsum[tid] = excl;
}

__global__ void k_fill(const int* __restrict__ ei) {
    int i = blockIdx.x * blockDim.x + threadIdx.x;
    if (i >= N_EDGES) return;
    int s = ei[i];
    int d = ei[N_EDGES + i];
    if (s < 0 || s >= N_NODES || d < 0 || d >= N_NODES) return;
    int pos = real_off(d) + atomicAdd(&g_fill[d], 1);
    g_srcs[pos] = s;
}

// ---------------- fused layer 1: agg(x)[6] then @W1[6,128]+b1, relu -> g_h1h
__global__ void k_aggx_gemm6(const float* __restrict__ x,
                             const float* __restrict__ W,
                             const float* __restrict__ b) {
    __shared__ float Asm[256][6];
    int tid = threadIdx.x;
    int node = blockIdx.x * 256 + tid;

    if (node < N_NODES) {
        float dd = g_dis[node];
        float s0 = dd * dd;
        const float2* xr = (const float2*)(x + node * 6);
        float2 a0 = xr[0], a1 = xr[1], a2 = xr[2];
        a0.x *= s0; a0.y *= s0; a1.x *= s0; a1.y *= s0; a2.x *= s0; a2.y *= s0;
        int beg = real_off(node), end = real_off(node + 1);
        for (int e = beg; e < end; e++) {
            int s = g_srcs[e];
            float w = g_dis[s] * dd;
            const float2* xs = (const float2*)(x + s * 6);
            float2 v0 = xs[0], v1 = xs[1], v2 = xs[2];
            a0.x += v0.x * w; a0.y += v0.y * w;
            a1.x += v1.x * w; a1.y += v1.y * w;
            a2.x += v2.x * w; a2.y += v2.y * w;
        }
        Asm[tid][0] = a0.x; Asm[tid][1] = a0.y;
        Asm[tid][2] = a1.x; Asm[tid][3] = a1.y;
        Asm[tid][4] = a2.x; Asm[tid][5] = a2.y;
    }
    __syncthreads();

    int j = tid & 63;
    int c0 = j * 2;
    float w0[6], w1[6];
    #pragma unroll
    for (int k = 0; k < 6; k++) {
        w0[k] = __ldg(&W[k * HID + c0]);
        w1[k] = __ldg(&W[k * HID + c0 + 1]);
    }
    float bb0 = __ldg(&b[c0]), bb1 = __ldg(&b[c0 + 1]);
    int nbase = blockIdx.x * 256;
    for (int r = tid >> 6; r < 256; r += 4) {
        int row = nbase + r;
        if (row >= N_NODES) break;
        float acc0 = bb0, acc1 = bb1;
        #pragma unroll
        for (int k = 0; k < 6; k++) {
            float a = Asm[r][k];
            acc0 += a * w0[k];
            acc1 += a * w1[k];
        }
        __half2 h = __floats2half2_rn(fmaxf(acc0, 0.f), fmaxf(acc1, 0.f));
        ((__half2*)(g_h1h + (size_t)row * HID))[j] = h;
    }
}

// ---------------- fused aggregate + split-fp16 HMMA GEMM
// dir=0: gather from g_h1h, write g_h2h;  dir=1: gather from g_h2h, write g_h1h.
// Phase 1: 8 warps x 16 nodes aggregation -> Ahi/Alo smem (hi/lo fp16 split).
// Phase 2: D = A @ W^T via 3 HMMA products (Ahi*Bhi + Ahi*Blo + Alo*Bhi), fp32 acc.
#define SA 136                                       // padded row stride (halfs)
#define SMEM_MMA_BYTES (4 * 128 * SA * 2 + 512)      // Ahi,Alo,Bhi,Blo + bias
__global__ void k_agg_gemm(const float* __restrict__ W, const float* __restrict__ b,
                           int dir) {
    extern __shared__ __half sm[];
    __half* Ahi = sm;
    __half* Alo = sm + 128 * SA;
    __half* Bhi = sm + 2 * 128 * SA;     // Bhi[n][k] = fp16(W[k][n])
    __half* Blo = sm + 3 * 128 * SA;
    float*  bs  = (float*)(sm + 4 * 128 * SA);
    const __half* hin = dir ? g_h2h : g_h1h;
    __half*       hout = dir ? g_h1h : g_h2h;
    int tid = threadIdx.x;
    int wid = tid >> 5, lane = tid & 31;
    int row0 = blockIdx.x * 128;

    // stage B = W^T hi/lo (coalesced W read)
    for (int idx = tid; idx < 128 * 128; idx += 256) {
        int k = idx >> 7, n = idx & 127;
        float w = __ldg(&W[idx]);
        __half hi = __float2half_rn(w);
        __half lo = __float2half_rn(w - __half2float(hi));
        Bhi[n * SA + k] = hi;
        Blo[n * SA + k] = lo;
    }
    if (tid < 128) bs[tid] = __ldg(&b[tid]);

    // phase 1: aggregate 16 nodes per warp, hi/lo split -> Ahi/Alo
    #pragma unroll 1
    for (int t = 0; t < 16; t++) {
        int r = wid * 16 + t;
        int node = row0 + r;
        float ax = 0.f, ay = 0.f, az = 0.f, aw = 0.f;
        if (node < N_NODES) {
            float dd = g_dis[node];
            float s0 = dd * dd;
            uint2 pv = ((const uint2*)(hin + (size_t)node * HID))[lane];
            float2 v0 = __half22float2(u32_as_h2(pv.x));
            float2 v1 = __half22float2(u32_as_h2(pv.y));
            ax = v0.x * s0; ay = v0.y * s0; az = v1.x * s0; aw = v1.y * s0;
            int beg = real_off(node), end = real_off(node + 1);
            for (int e = beg; e < end; e++) {
                int s = g_srcs[e];
                float w = g_dis[s] * dd;
                uint2 ph = ((const uint2*)(hin + (size_t)s * HID))[lane];
                float2 h0 = __half22float2(u32_as_h2(ph.x));
                float2 h1 = __half22float2(u32_as_h2(ph.y));
                ax += h0.x * w;
                ay += h0.y * w;
                az += h1.x * w;
                aw += h1.y * w;
            }
        }
        __half hx = __float2half_rn(ax), hy = __float2half_rn(ay);
        __half hz = __float2half_rn(az), hw = __float2half_rn(aw);
        __half lx = __float2half_rn(ax - __half2float(hx));
        __half ly = __float2half_rn(ay - __half2float(hy));
        __half lz = __float2half_rn(az - __half2float(hz));
        __half lw = __float2half_rn(aw - __half2float(hw));
        uint2 ph2, pl2;
        ph2.x = h2_as_u32(__halves2half2(hx, hy));
        ph2.y = h2_as_u32(__halves2half2(hz, hw));
        pl2.x = h2_as_u32(__halves2half2(lx, ly));
        pl2.y = h2_as_u32(__halves2half2(lz, lw));
        *(uint2*)(Ahi + r * SA + lane * 4) = ph2;
        *(uint2*)(Alo + r * SA + lane * 4) = pl2;
    }
    __syncthreads();

    uint32_t ahi_base = smem_u32(Ahi), alo_base = smem_u32(Alo);
    uint32_t bhi_base = smem_u32(Bhi), blo_base = smem_u32(Blo);
    int R0 = wid * 16;

    float d[16][4];
    #pragma unroll
    for (int nt = 0; nt < 16; nt++)
        #pragma unroll
        for (int q = 0; q < 4; q++) d[nt][q] = 0.f;

    #pragma unroll
    for (int kt = 0; kt < 8; kt++) {
        int k0 = kt * 16;
        uint32_t aoff =
            ((uint32_t)((R0 + (lane & 15)) * SA + k0 + ((lane >> 4) << 3)) << 1);
        uint32_t ah0, ah1, ah2, ah3, al0, al1, al2, al3;
        asm volatile("ldmatrix.sync.aligned.m8n8.x4.shared.b16 {%0,%1,%2,%3}, [%4];"
                     : "=r"(ah0), "=r"(ah1), "=r"(ah2), "=r"(ah3) : "r"(ahi_base + aoff));
        asm volatile("ldmatrix.sync.aligned.m8n8.x4.shared.b16 {%0,%1,%2,%3}, [%4];"
                     : "=r"(al0), "=r"(al1), "=r"(al2), "=r"(al3) : "r"(alo_base + aoff));
        #pragma unroll
        for (int nt = 0; nt < 16; nt++) {
            int n0 = nt * 8;
            uint32_t boff =
                ((uint32_t)((n0 + (lane & 7)) * SA + k0 + (lane & 8)) << 1);
            uint32_t bh0, bh1, bl0, bl1;
            asm volatile("ldmatrix.sync.aligned.m8n8.x2.shared.b16 {%0,%1}, [%2];"
                         : "=r"(bh0), "=r"(bh1) : "r"(bhi_base + boff));
            asm volatile("ldmatrix.sync.aligned.m8n8.x2.shared.b16 {%0,%1}, [%2];"
                         : "=r"(bl0), "=r"(bl1) : "r"(blo_base + boff));
            asm volatile(
                "mma.sync.aligned.m16n8k16.row.col.f32.f16.f16.f32 "
                "{%0,%1,%2,%3}, {%4,%5,%6,%7}, {%8,%9}, {%0,%1,%2,%3};"
                : "+f"(d[nt][0]), "+f"(d[nt][1]), "+f"(d[nt][2]), "+f"(d[nt][3])
                : "r"(ah0), "r"(ah1), "r"(ah2), "r"(ah3), "r"(bh0), "r"(bh1));
            asm volatile(
                "mma.sync.aligned.m16n8k16.row.col.f32.f16.f16.f32 "
                "{%0,%1,%2,%3}, {%4,%5,%6,%7}, {%8,%9}, {%0,%1,%2,%3};"
                : "+f"(d[nt][0]), "+f"(d[nt][1]), "+f"(d[nt][2]), "+f"(d[nt][3])
                : "r"(ah0), "r"(ah1), "r"(ah2), "r"(ah3), "r"(bl0), "r"(bl1));
            asm volatile(
                "mma.sync.aligned.m16n8k16.row.col.f32.f16.f16.f32 "
                "{%0,%1,%2,%3}, {%4,%5,%6,%7}, {%8,%9}, {%0,%1,%2,%3};"
                : "+f"(d[nt][0]), "+f"(d[nt][1]), "+f"(d[nt][2]), "+f"(d[nt][3])
                : "r"(al0), "r"(al1), "r"(al2), "r"(al3), "r"(bh0), "r"(bh1));
        }
    }

    // epilogue: bias + relu + fp16 pack
    int rA = row0 + R0 + (lane >> 2);
    int rB = rA + 8;
    int cl = (lane & 3) * 2;
    #pragma unroll
    for (int nt = 0; nt < 16; nt++) {
        int n0 = nt * 8 + cl;
        float bb0 = bs[n0], bb1 = bs[n0 + 1];
        if (rA < N_NODES) {
            __half2 h = __floats2half2_rn(fmaxf(d[nt][0] + bb0, 0.f),
                                          fmaxf(d[nt][1] + bb1, 0.f));
            *(__half2*)(hout + (size_t)rA * HID + n0) = h;
        }
        if (rB < N_NODES) {
            __half2 h = __floats2half2_rn(fmaxf(d[nt][2] + bb0, 0.f),
                                          fmaxf(d[nt][3] + bb1, 0.f));
            *(__half2*)(hout + (size_t)rB * HID + n0) = h;
        }
    }
}

// ---------------- fused pool + fc1 + fc2 ----------------
__global__ void k_pool_fc(const float* __restrict__ fc1_w, const float* __restrict__ fc1_b,
                          const float* __restrict__ fc2_w, const float* __restrict__ fc2_b,
                          float* __restrict__ out) {
    __shared__ float pooled[HID];
    __shared__ float z[64];
    int g = blockIdx.x, c = threadIdx.x;
    int s = g_gstart[g], e = g_gstart[g + 1];
    float acc = 0.f;
    for (int i = s; i < e; i++) acc += __half2float(g_h1h[(size_t)i * HID + c]);
    float cnt = (float)((e - s) > 1 ? (e - s) : 1);
    pooled[c] = acc / cnt;
    __syncthreads();
    if (c < 64) {
        float a = fc1_b[c];
        #pragma unroll 8
        for (int k = 0; k < HID; k++) a += pooled[k] * fc1_w[k * 64 + c];
        z[c] = fmaxf(a, 0.f);
    }
    __syncthreads();
    if (c == 0) {
        float a = fc2_b[0];
        #pragma unroll 8
        for (int j = 0; j < 64; j++) a += z[j] * fc2_w[j];
        out[g] = a;
    }
}

// ---------------- launch ----------------
extern "C" void kernel_launch(void* const* d_in, const int* in_sizes, int n_in,
                              void* d_out, int out_size) {
    const float* x     = (const float*)d_in[0];
    const int*   ei    = (const int*)d_in[1];   // int64 narrowed to int32 by harness
    const int*   batch = (const int*)d_in[2];
    const float* W1 = (const float*)d_in[3];
    const float* b1 = (const float*)d_in[4];
    const float* W2 = (const float*)d_in[5];
    const float* b2 = (const float*)d_in[6];
    const float* W3 = (const float*)d_in[7];
    const float* b3 = (const float*)d_in[8];
    const float* fc1_w = (const float*)d_in[9];
    const float* fc1_b = (const float*)d_in[10];
    const float* fc2_w = (const float*)d_in[11];
    const float* fc2_b = (const float*)d_in[12];
    float* out = (float*)d_out;

    cudaFuncSetAttribute(k_agg_gemm,
                         cudaFuncAttributeMaxDynamicSharedMemorySize, SMEM_MMA_BYTES);

    k_init<<<256, 256>>>();
    k_degree<<<(N_EDGES + 255) / 256, 256>>>(ei);
    k_scan1<<<SCAN_NB, 256>>>(batch);
    k_scan2<<<1, 256>>>();
    k_fill<<<(N_EDGES + 255) / 256, 256>>>(ei);

    const int TC_BLOCKS = (N_NODES + 127) / 128;   // 391

    // layer 1 (fused agg + 6x128 gemm) -> g_h1h
    k_aggx_gemm6<<<(N_NODES + 255) / 256, 256>>>(x, W1, b1);
    // layer 2 (fused agg + gemm): g_h1h -> g_h2h
    k_agg_gemm<<<TC_BLOCKS, 256, SMEM_MMA_BYTES>>>(W2, b2, 0);
    // layer 3 (fused agg + gemm): g_h2h -> g_h1h
    k_agg_gemm<<<TC_BLOCKS, 256, SMEM_MMA_BYTES>>>(W3, b3, 1);

    // fused pool + MLP
    k_pool_fc<<<N_GRAPHS, HID>>>(fc1_w, fc1_b, fc2_w, fc2_b, out);
}

// round 14
// speedup vs baseline: 1.3900x; 1.3900x over previous
#include <cuda_runtime.h>
#include <cuda_fp16.h>
#include <cuda_bf16.h>
#include <cstdint>

#define N_NODES 50000
#define N_EDGES 600000
#define N_GRAPHS 64
#define HID 128
#define SCAN_NB ((N_NODES + 255) / 256)   // 196

__device__ __forceinline__ unsigned int h2_as_u32(__half2 h) {
    return *reinterpret_cast<unsigned int*>(&h);
}
__device__ __forceinline__ __half2 u32_as_h2(unsigned int u) {
    return *reinterpret_cast<__half2*>(&u);
}
__device__ __forceinline__ uint32_t smem_u32(const void* p) {
    uint32_t a;
    asm("{ .reg .u64 t; cvta.to.shared.u64 t, %1; cvt.u32.u64 %0, t; }" : "=r"(a) : "l"(p));
    return a;
}

// ---------------- scratch (static device globals; no allocation) ----------------
__device__ int    g_indeg[N_NODES];
__device__ float  g_dis[N_NODES];
__device__ int    g_offs[N_NODES + 1];
__device__ int    g_fill[N_NODES];
__device__ int    g_srcs[N_EDGES];
__device__ int    g_bsum[256];
__device__ float  g_h0[(size_t)N_NODES * HID];   // agg output (fp32, GEMM A operand)
__device__ __half g_h1h[(size_t)N_NODES * HID];  // GEMM output (fp16, gathered)
__device__ int    g_gstart[N_GRAPHS + 1];
// precomputed W^T hi/lo fp16 [n][k]: index 0 = W2, 1 = W3
__device__ __half g_whi[2][HID * HID];
__device__ __half g_wlo[2][HID * HID];

__device__ __forceinline__ int real_off(int i) { return g_offs[i] + g_bsum[i >> 8]; }

// ---------------- graph preprocessing ----------------
__global__ void k_init() {
    for (int i = blockIdx.x * blockDim.x + threadIdx.x; i < N_NODES;
         i += gridDim.x * blockDim.x) {
        g_indeg[i] = 0;
        g_fill[i] = 0;
    }
}

__global__ void k_degree(const int* __restrict__ ei) {
    int i = blockIdx.x * blockDim.x + threadIdx.x;
    if (i >= N_EDGES) return;
    int d = ei[N_EDGES + i];
    if (d >= 0 && d < N_NODES) atomicAdd(&g_indeg[d], 1);
}

__global__ void k_scan1(const int* __restrict__ batch) {
    __shared__ int wsum[8];
    int tid = threadIdx.x, lane = tid & 31, wid = tid >> 5;
    int i = blockIdx.x * 256 + tid;
    int v = (i < N_NODES) ? g_indeg[i] : 0;
    if (i < N_NODES) g_dis[i] = rsqrtf((float)(v + 1));
    int s = v;
    #pragma unroll
    for (int o = 1; o < 32; o <<= 1) {
        int t = __shfl_up_sync(0xffffffffu, s, o);
        if (lane >= o) s += t;
    }
    if (lane == 31) wsum[wid] = s;
    __syncthreads();
    if (tid == 0) {
        int run = 0;
        #pragma unroll
        for (int j = 0; j < 8; j++) { int t = wsum[j]; wsum[j] = run; run += t; }
        g_bsum[blockIdx.x] = run;
    }
    __syncthreads();
    int excl = wsum[wid] + (s - v);
    if (i <= N_NODES) g_offs[i] = excl;

    if (i < N_NODES) {
        int b = batch[i];
        if (b < 0) b = 0;
        if (b >= N_GRAPHS) b = N_GRAPHS - 1;
        int prev;
        if (i == 0) prev = -1;
        else {
            prev = batch[i - 1];
            if (prev < 0) prev = 0;
            if (prev >= N_GRAPHS) prev = N_GRAPHS - 1;
        }
        for (int g = prev + 1; g <= b; g++) g_gstart[g] = i;
        if (i == N_NODES - 1)
            for (int g = b + 1; g <= N_GRAPHS; g++) g_gstart[g] = N_NODES;
    }
}

__global__ void k_scan2() {
    __shared__ int wsum[8];
    int tid = threadIdx.x, lane = tid & 31, wid = tid >> 5;
    int v = (tid < SCAN_NB) ? g_bsum[tid] : 0;
    int s = v;
    #pragma unroll
    for (int o = 1; o < 32; o <<= 1) {
        int t = __shfl_up_sync(0xffffffffu, s, o);
        if (lane >= o) s += t;
    }
    if (lane == 31) wsum[wid] = s;
    __syncthreads();
    if (tid == 0) {
        int run = 0;
        #pragma unroll
        for (int j = 0; j < 8; j++) { int t = wsum[j]; wsum[j] = run; run += t; }
    }
    __syncthreads();
    int excl = wsum[wid] + (s - v);
    if (tid < SCAN_NB) g_bsum[tid] = excl;
}

__global__ void k_fill(const int* __restrict__ ei) {
    int i = blockIdx.x * blockDim.x + threadIdx.x;
    if (i >= N_EDGES) return;
    int s = ei[i];
    int d = ei[N_EDGES + i];
    if (s < 0 || s >= N_NODES || d < 0 || d >= N_NODES) return;
    int pos = real_off(d) + atomicAdd(&g_fill[d], 1);
    g_srcs[pos] = s;
}

// ---------------- W2/W3 -> transposed hi/lo fp16 (once per call) ----------------
__global__ void k_wsplit(const float* __restrict__ W2, const float* __restrict__ W3) {
    int idx = blockIdx.x * 256 + threadIdx.x;   // 2 * 16384
    int m = idx >> 14;                          // 0: W2, 1: W3
    int e = idx & 16383;
    int k = e >> 7, n = e & 127;
    const float* W = m ? W3 : W2;
    float w = __ldg(&W[e]);
    __half hi = __float2half_rn(w);
    __half lo = __float2half_rn(w - __half2float(hi));
    g_whi[m][n * HID + k] = hi;
    g_wlo[m][n * HID + k] = lo;
}

// ---------------- fused layer 1: agg(x)[6] then @W1[6,128]+b1, relu -> g_h1h
__global__ void k_aggx_gemm6(const float* __restrict__ x,
                             const float* __restrict__ W,
                             const float* __restrict__ b) {
    __shared__ float Asm[256][6];
    int tid = threadIdx.x;
    int node = blockIdx.x * 256 + tid;

    if (node < N_NODES) {
        float dd = g_dis[node];
        float s0 = dd * dd;
        const float2* xr = (const float2*)(x + node * 6);
        float2 a0 = xr[0], a1 = xr[1], a2 = xr[2];
        a0.x *= s0; a0.y *= s0; a1.x *= s0; a1.y *= s0; a2.x *= s0; a2.y *= s0;
        int beg = real_off(node), end = real_off(node + 1);
        for (int e = beg; e < end; e++) {
            int s = g_srcs[e];
            float w = g_dis[s] * dd;
            const float2* xs = (const float2*)(x + s * 6);
            float2 v0 = xs[0], v1 = xs[1], v2 = xs[2];
            a0.x += v0.x * w; a0.y += v0.y * w;
            a1.x += v1.x * w; a1.y += v1.y * w;
            a2.x += v2.x * w; a2.y += v2.y * w;
        }
        Asm[tid][0] = a0.x; Asm[tid][1] = a0.y;
        Asm[tid][2] = a1.x; Asm[tid][3] = a1.y;
        Asm[tid][4] = a2.x; Asm[tid][5] = a2.y;
    }
    __syncthreads();

    int j = tid & 63;
    int c0 = j * 2;
    float w0[6], w1[6];
    #pragma unroll
    for (int k = 0; k < 6; k++) {
        w0[k] = __ldg(&W[k * HID + c0]);
        w1[k] = __ldg(&W[k * HID + c0 + 1]);
    }
    float bb0 = __ldg(&b[c0]), bb1 = __ldg(&b[c0 + 1]);
    int nbase = blockIdx.x * 256;
    for (int r = tid >> 6; r < 256; r += 4) {
        int row = nbase + r;
        if (row >= N_NODES) break;
        float acc0 = bb0, acc1 = bb1;
        #pragma unroll
        for (int k = 0; k < 6; k++) {
            float a = Asm[r][k];
            acc0 += a * w0[k];
            acc1 += a * w1[k];
        }
        __half2 h = __floats2half2_rn(fmaxf(acc0, 0.f), fmaxf(acc1, 0.f));
        ((__half2*)(g_h1h + (size_t)row * HID))[j] = h;
    }
}

// ---------------- split-fp16 HMMA GEMM: g_h0[N,128](f32) @ W[128,128] + b, relu -> g_h1h
#define SA 136                                       // padded row stride (halfs)
#define SMEM_MMA_BYTES (4 * 128 * SA * 2 + 512)      // Ahi,Alo,Bhi,Blo + bias
__global__ void k_gemm128_mma(const float* __restrict__ b, int which) {
    extern __shared__ __half sm[];
    __half* Ahi = sm;
    __half* Alo = sm + 128 * SA;
    __half* Bhi = sm + 2 * 128 * SA;     // Bhi[n][k]
    __half* Blo = sm + 3 * 128 * SA;
    float*  bs  = (float*)(sm + 4 * 128 * SA);
    int tid = threadIdx.x;
    int wid = tid >> 5, lane = tid & 31;
    int row0 = blockIdx.x * 128;

    // stage A tile (fp32 rows from g_h0 -> hi/lo fp16), zero-pad OOB rows
    for (int idx = tid; idx < 128 * 32; idx += 256) {
        int r = idx >> 5, q = idx & 31;
        float4 v = make_float4(0.f, 0.f, 0.f, 0.f);
        int row = row0 + r;
        if (row < N_NODES) v = ((const float4*)(g_h0 + (size_t)row * HID))[q];
        __half hx = __float2half_rn(v.x), hy = __float2half_rn(v.y);
        __half hz = __float2half_rn(v.z), hw = __float2half_rn(v.w);
        __half lx = __float2half_rn(v.x - __half2float(hx));
        __half ly = __float2half_rn(v.y - __half2float(hy));
        __half lz = __float2half_rn(v.z - __half2float(hz));
        __half lw = __float2half_rn(v.w - __half2float(hw));
        uint2 ph, pl;
        ph.x = h2_as_u32(__halves2half2(hx, hy));
        ph.y = h2_as_u32(__halves2half2(hz, hw));
        pl.x = h2_as_u32(__halves2half2(lx, ly));
        pl.y = h2_as_u32(__halves2half2(lz, lw));
        *(uint2*)(Ahi + r * SA + q * 4) = ph;
        *(uint2*)(Alo + r * SA + q * 4) = pl;
    }
    // stage B from precomputed hi/lo [n][k] (uint4 copies, coalesced)
    {
        const __half* whi = g_whi[which];
        const __half* wlo = g_wlo[which];
        for (int idx = tid; idx < 128 * 16; idx += 256) {
            int n = idx >> 4, seg = idx & 15;
            *(uint4*)(Bhi + n * SA + seg * 8) = *(const uint4*)(whi + n * HID + seg * 8);
            *(uint4*)(Blo + n * SA + seg * 8) = *(const uint4*)(wlo + n * HID + seg * 8);
        }
    }
    if (tid < 128) bs[tid] = __ldg(&b[tid]);
    __syncthreads();

    uint32_t ahi_base = smem_u32(Ahi), alo_base = smem_u32(Alo);
    uint32_t bhi_base = smem_u32(Bhi), blo_base = smem_u32(Blo);
    int R0 = wid * 16;

    float d[16][4];
    #pragma unroll
    for (int nt = 0; nt < 16; nt++)
        #pragma unroll
        for (int q = 0; q < 4; q++) d[nt][q] = 0.f;

    #pragma unroll
    for (int kt = 0; kt < 8; kt++) {
        int k0 = kt * 16;
        uint32_t aoff =
            ((uint32_t)((R0 + (lane & 15)) * SA + k0 + ((lane >> 4) << 3)) << 1);
        uint32_t ah0, ah1, ah2, ah3, al0, al1, al2, al3;
        asm volatile("ldmatrix.sync.aligned.m8n8.x4.shared.b16 {%0,%1,%2,%3}, [%4];"
                     : "=r"(ah0), "=r"(ah1), "=r"(ah2), "=r"(ah3) : "r"(ahi_base + aoff));
        asm volatile("ldmatrix.sync.aligned.m8n8.x4.shared.b16 {%0,%1,%2,%3}, [%4];"
                     : "=r"(al0), "=r"(al1), "=r"(al2), "=r"(al3) : "r"(alo_base + aoff));
        #pragma unroll
        for (int nt = 0; nt < 16; nt++) {
            int n0 = nt * 8;
            uint32_t boff =
                ((uint32_t)((n0 + (lane & 7)) * SA + k0 + (lane & 8)) << 1);
            uint32_t bh0, bh1, bl0, bl1;
            asm volatile("ldmatrix.sync.aligned.m8n8.x2.shared.b16 {%0,%1}, [%2];"
                         : "=r"(bh0), "=r"(bh1) : "r"(bhi_base + boff));
            asm volatile("ldmatrix.sync.aligned.m8n8.x2.shared.b16 {%0,%1}, [%2];"
                         : "=r"(bl0), "=r"(bl1) : "r"(blo_base + boff));
            asm volatile(
                "mma.sync.aligned.m16n8k16.row.col.f32.f16.f16.f32 "
                "{%0,%1,%2,%3}, {%4,%5,%6,%7}, {%8,%9}, {%0,%1,%2,%3};"
                : "+f"(d[nt][0]), "+f"(d[nt][1]), "+f"(d[nt][2]), "+f"(d[nt][3])
                : "r"(ah0), "r"(ah1), "r"(ah2), "r"(ah3), "r"(bh0), "r"(bh1));
            asm volatile(
                "mma.sync.aligned.m16n8k16.row.col.f32.f16.f16.f32 "
                "{%0,%1,%2,%3}, {%4,%5,%6,%7}, {%8,%9}, {%0,%1,%2,%3};"
                : "+f"(d[nt][0]), "+f"(d[nt][1]), "+f"(d[nt][2]), "+f"(d[nt][3])
                : "r"(ah0), "r"(ah1), "r"(ah2), "r"(ah3), "r"(bl0), "r"(bl1));
            asm volatile(
                "mma.sync.aligned.m16n8k16.row.col.f32.f16.f16.f32 "
                "{%0,%1,%2,%3}, {%4,%5,%6,%7}, {%8,%9}, {%0,%1,%2,%3};"
                : "+f"(d[nt][0]), "+f"(d[nt][1]), "+f"(d[nt][2]), "+f"(d[nt][3])
                : "r"(al0), "r"(al1), "r"(al2), "r"(al3), "r"(bh0), "r"(bh1));
        }
    }

    // epilogue: bias + relu + fp16 pack
    int rA = row0 + R0 + (lane >> 2);
    int rB = rA + 8;
    int cl = (lane & 3) * 2;
    #pragma unroll
    for (int nt = 0; nt < 16; nt++) {
        int n0 = nt * 8 + cl;
        float bb0 = bs[n0], bb1 = bs[n0 + 1];
        if (rA < N_NODES) {
            __half2 h = __floats2half2_rn(fmaxf(d[nt][0] + bb0, 0.f),
                                          fmaxf(d[nt][1] + bb1, 0.f));
            *(__half2*)(g_h1h + (size_t)rA * HID + n0) = h;
        }
        if (rB < N_NODES) {
            __half2 h = __floats2half2_rn(fmaxf(d[nt][2] + bb0, 0.f),
                                          fmaxf(d[nt][3] + bb1, 0.f));
            *(__half2*)(g_h1h + (size_t)rB * HID + n0) = h;
        }
    }
}

// ---------------- 128-dim aggregation: gathers fp16 g_h1h, writes fp32 g_h0
__global__ void k_aggregate() {
    int node = blockIdx.x * (blockDim.x >> 5) + (threadIdx.x >> 5);
    if (node >= N_NODES) return;
    int lane = threadIdx.x & 31;
    float dd = g_dis[node];
    float s0 = dd * dd;
    uint2 pv = ((const uint2*)(g_h1h + (size_t)node * HID))[lane];
    float2 v0 = __half22float2(u32_as_h2(pv.x));
    float2 v1 = __half22float2(u32_as_h2(pv.y));
    float ax = v0.x * s0, ay = v0.y * s0, az = v1.x * s0, aw = v1.y * s0;
    int beg = real_off(node), end = real_off(node + 1);
    for (int e = beg; e < end; e++) {
        int s = g_srcs[e];
        float w = g_dis[s] * dd;
        uint2 ph = ((const uint2*)(g_h1h + (size_t)s * HID))[lane];
        float2 h0 = __half22float2(u32_as_h2(ph.x));
        float2 h1 = __half22float2(u32_as_h2(ph.y));
        ax += h0.x * w;
        ay += h0.y * w;
        az += h1.x * w;
        aw += h1.y * w;
    }
    ((float4*)(g_h0 + (size_t)node * HID))[lane] = make_float4(ax, ay, az, aw);
}

// ---------------- fused pool + fc1 + fc2 ----------------
__global__ void k_pool_fc(const float* __restrict__ fc1_w, const float* __restrict__ fc1_b,
                          const float* __restrict__ fc2_w, const float* __restrict__ fc2_b,
                          float* __restrict__ out) {
    __shared__ float pooled[HID];
    __shared__ float z[64];
    int g = blockIdx.x, c = threadIdx.x;
    int s = g_gstart[g], e = g_gstart[g + 1];
    float acc = 0.f;
    for (int i = s; i < e; i++) acc += __half2float(g_h1h[(size_t)i * HID + c]);
    float cnt = (float)((e - s) > 1 ? (e - s) : 1);
    pooled[c] = acc / cnt;
    __syncthreads();
    if (c < 64) {
        float a = fc1_b[c];
        #pragma unroll 8
        for (int k = 0; k < HID; k++) a += pooled[k] * fc1_w[k * 64 + c];
        z[c] = fmaxf(a, 0.f);
    }
    __syncthreads();
    if (c == 0) {
        float a = fc2_b[0];
        #pragma unroll 8
        for (int j = 0; j < 64; j++) a += z[j] * fc2_w[j];
        out[g] = a;
    }
}

// ---------------- launch ----------------
extern "C" void kernel_launch(void* const* d_in, const int* in_sizes, int n_in,
                              void* d_out, int out_size) {
    const float* x     = (const float*)d_in[0];
    const int*   ei    = (const int*)d_in[1];   // int64 narrowed to int32 by harness
    const int*   batch = (const int*)d_in[2];
    const float* W1 = (const float*)d_in[3];
    const float* b1 = (const float*)d_in[4];
    const float* W2 = (const float*)d_in[5];
    const float* b2 = (const float*)d_in[6];
    const float* W3 = (const float*)d_in[7];
    const float* b3 = (const float*)d_in[8];
    const float* fc1_w = (const float*)d_in[9];
    const float* fc1_b = (const float*)d_in[10];
    const float* fc2_w = (const float*)d_in[11];
    const float* fc2_b = (const float*)d_in[12];
    float* out = (float*)d_out;

    cudaFuncSetAttribute(k_gemm128_mma,
                         cudaFuncAttributeMaxDynamicSharedMemorySize, SMEM_MMA_BYTES);

    k_init<<<256, 256>>>();
    k_degree<<<(N_EDGES + 255) / 256, 256>>>(ei);
    k_scan1<<<SCAN_NB, 256>>>(batch);
    k_scan2<<<1, 256>>>();
    k_fill<<<(N_EDGES + 255) / 256, 256>>>(ei);
    k_wsplit<<<128, 256>>>(W2, W3);

    const int AGG_BLOCKS = (N_NODES + 7) / 8;
    const int TC_BLOCKS = (N_NODES + 127) / 128;   // 391

    // layer 1 (fused agg + 6x128 gemm)
    k_aggx_gemm6<<<(N_NODES + 255) / 256, 256>>>(x, W1, b1);
    // layer 2
    k_aggregate<<<AGG_BLOCKS, 256>>>();
    k_gemm128_mma<<<TC_BLOCKS, 256, SMEM_MMA_BYTES>>>(b2, 0);
    // layer 3
    k_aggregate<<<AGG_BLOCKS, 256>>>();
    k_gemm128_mma<<<TC_BLOCKS, 256, SMEM_MMA_BYTES>>>(b3, 1);

    // fused pool + MLP
    k_pool_fc<<<N_GRAPHS, HID>>>(fc1_w, fc1_b, fc2_w, fc2_b, out);
}

// round 15
// speedup vs baseline: 1.5107x; 1.0868x over previous
#include <cuda_runtime.h>
#include <cuda_fp16.h>
#include <cuda_bf16.h>
#include <cstdint>

#define N_NODES 50000
#define N_EDGES 600000
#define N_GRAPHS 64
#define HID 128
#define SCAN_NB ((N_NODES + 255) / 256)   // 196

__device__ __forceinline__ unsigned int h2_as_u32(__half2 h) {
    return *reinterpret_cast<unsigned int*>(&h);
}
__device__ __forceinline__ __half2 u32_as_h2(unsigned int u) {
    return *reinterpret_cast<__half2*>(&u);
}
__device__ __forceinline__ uint32_t smem_u32(const void* p) {
    uint32_t a;
    asm("{ .reg .u64 t; cvta.to.shared.u64 t, %1; cvt.u32.u64 %0, t; }" : "=r"(a) : "l"(p));
    return a;
}

// ---------------- scratch (static device globals; no allocation) ----------------
__device__ int    g_indeg[N_NODES];
__device__ float  g_dis[N_NODES];
__device__ int    g_offs[N_NODES + 1];
__device__ int    g_fill[N_NODES];
__device__ int    g_srcs[N_EDGES];
__device__ int    g_bsum[256];
__device__ float  g_h0[(size_t)N_NODES * HID];   // agg output (fp32, GEMM A operand)
__device__ __half g_h1h[(size_t)N_NODES * HID];  // GEMM output (fp16, gathered)
__device__ int    g_gstart[N_GRAPHS + 1];
// precomputed W^T hi/lo fp16 [n][k]: index 0 = W2, 1 = W3
__device__ __half g_whi[2][HID * HID];
__device__ __half g_wlo[2][HID * HID];

__device__ __forceinline__ int real_off(int i) { return g_offs[i] + g_bsum[i >> 8]; }

// ---------------- init (zero counters) + W2/W3 hi/lo split, fused ----------------
__global__ void k_init_wsplit(const float* __restrict__ W2, const float* __restrict__ W3) {
    int gidx = blockIdx.x * blockDim.x + threadIdx.x;
    for (int i = gidx; i < N_NODES; i += gridDim.x * blockDim.x) {
        g_indeg[i] = 0;
        g_fill[i] = 0;
    }
    if (gidx < 2 * HID * HID) {
        int m = gidx >> 14;                     // 0: W2, 1: W3
        int e = gidx & 16383;
        int k = e >> 7, n = e & 127;
        const float* W = m ? W3 : W2;
        float w = __ldg(&W[e]);
        __half hi = __float2half_rn(w);
        __half lo = __float2half_rn(w - __half2float(hi));
        g_whi[m][n * HID + k] = hi;
        g_wlo[m][n * HID + k] = lo;
    }
}

__global__ void k_degree(const int* __restrict__ ei) {
    int i = blockIdx.x * blockDim.x + threadIdx.x;
    if (i >= N_EDGES) return;
    int d = ei[N_EDGES + i];
    if (d >= 0 && d < N_NODES) atomicAdd(&g_indeg[d], 1);
}

__global__ void k_scan1(const int* __restrict__ batch) {
    __shared__ int wsum[8];
    int tid = threadIdx.x, lane = tid & 31, wid = tid >> 5;
    int i = blockIdx.x * 256 + tid;
    int v = (i < N_NODES) ? g_indeg[i] : 0;
    if (i < N_NODES) g_dis[i] = rsqrtf((float)(v + 1));
    int s = v;
    #pragma unroll
    for (int o = 1; o < 32; o <<= 1) {
        int t = __shfl_up_sync(0xffffffffu, s, o);
        if (lane >= o) s += t;
    }
    if (lane == 31) wsum[wid] = s;
    __syncthreads();
    if (tid == 0) {
        int run = 0;
        #pragma unroll
        for (int j = 0; j < 8; j++) { int t = wsum[j]; wsum[j] = run; run += t; }
        g_bsum[blockIdx.x] = run;
    }
    __syncthreads();
    int excl = wsum[wid] + (s - v);
    if (i <= N_NODES) g_offs[i] = excl;

    if (i < N_NODES) {
        int b = batch[i];
        if (b < 0) b = 0;
        if (b >= N_GRAPHS) b = N_GRAPHS - 1;
        int prev;
        if (i == 0) prev = -1;
        else {
            prev = batch[i - 1];
            if (prev < 0) prev = 0;
            if (prev >= N_GRAPHS) prev = N_GRAPHS - 1;
        }
        for (int g = prev + 1; g <= b; g++) g_gstart[g] = i;
        if (i == N_NODES - 1)
            for (int g = b + 1; g <= N_GRAPHS; g++) g_gstart[g] = N_NODES;
    }
}

__global__ void k_scan2() {
    __shared__ int wsum[8];
    int tid = threadIdx.x, lane = tid & 31, wid = tid >> 5;
    int v = (tid < SCAN_NB) ? g_bsum[tid] : 0;
    int s = v;
    #pragma unroll
    for (int o = 1; o < 32; o <<= 1) {
        int t = __shfl_up_sync(0xffffffffu, s, o);
        if (lane >= o) s += t;
    }
    if (lane == 31) wsum[wid] = s;
    __syncthreads();
    if (tid == 0) {
        int run = 0;
        #pragma unroll
        for (int j = 0; j < 8; j++) { int t = wsum[j]; wsum[j] = run; run += t; }
    }
    __syncthreads();
    int excl = wsum[wid] + (s - v);
    if (tid < SCAN_NB) g_bsum[tid] = excl;
}

__global__ void k_fill(const int* __restrict__ ei) {
    int i = blockIdx.x * blockDim.x + threadIdx.x;
    if (i >= N_EDGES) return;
    int s = ei[i];
    int d = ei[N_EDGES + i];
    if (s < 0 || s >= N_NODES || d < 0 || d >= N_NODES) return;
    int pos = real_off(d) + atomicAdd(&g_fill[d], 1);
    g_srcs[pos] = s;
}

// ---------------- fused layer 1: agg(x)[6] then @W1[6,128]+b1, relu -> g_h1h
__global__ void k_aggx_gemm6(const float* __restrict__ x,
                             const float* __restrict__ W,
                             const float* __restrict__ b) {
    __shared__ float Asm[256][6];
    int tid = threadIdx.x;
    int node = blockIdx.x * 256 + tid;

    if (node < N_NODES) {
        float dd = g_dis[node];
        float s0 = dd * dd;
        const float2* xr = (const float2*)(x + node * 6);
        float2 a0 = xr[0], a1 = xr[1], a2 = xr[2];
        a0.x *= s0; a0.y *= s0; a1.x *= s0; a1.y *= s0; a2.x *= s0; a2.y *= s0;
        int beg = real_off(node), end = real_off(node + 1);
        for (int e = beg; e < end; e++) {
            int s = g_srcs[e];
            float w = g_dis[s] * dd;
            const float2* xs = (const float2*)(x + s * 6);
            float2 v0 = xs[0], v1 = xs[1], v2 = xs[2];
            a0.x += v0.x * w; a0.y += v0.y * w;
            a1.x += v1.x * w; a1.y += v1.y * w;
            a2.x += v2.x * w; a2.y += v2.y * w;
        }
        Asm[tid][0] = a0.x; Asm[tid][1] = a0.y;
        Asm[tid][2] = a1.x; Asm[tid][3] = a1.y;
        Asm[tid][4] = a2.x; Asm[tid][5] = a2.y;
    }
    __syncthreads();

    int j = tid & 63;
    int c0 = j * 2;
    float w0[6], w1[6];
    #pragma unroll
    for (int k = 0; k < 6; k++) {
        w0[k] = __ldg(&W[k * HID + c0]);
        w1[k] = __ldg(&W[k * HID + c0 + 1]);
    }
    float bb0 = __ldg(&b[c0]), bb1 = __ldg(&b[c0 + 1]);
    int nbase = blockIdx.x * 256;
    for (int r = tid >> 6; r < 256; r += 4) {
        int row = nbase + r;
        if (row >= N_NODES) break;
        float acc0 = bb0, acc1 = bb1;
        #pragma unroll
        for (int k = 0; k < 6; k++) {
            float a = Asm[r][k];
            acc0 += a * w0[k];
            acc1 += a * w1[k];
        }
        __half2 h = __floats2half2_rn(fmaxf(acc0, 0.f), fmaxf(acc1, 0.f));
        ((__half2*)(g_h1h + (size_t)row * HID))[j] = h;
    }
}

// ---------------- split-fp16 HMMA GEMM: g_h0[N,128](f32) @ W[128,128] + b, relu -> g_h1h
// Tile: 64 rows x 128 cols per CTA (smem ~102.5KB -> 2 CTAs/SM).
// 8 warps = 4 row-groups x 2 N-halves; each warp 16 rows x 64 cols.
#define SA 136                                          // padded row stride (halfs)
#define SMEM_MMA_BYTES ((64 + 64 + 128 + 128) * SA * 2 + 512)
__global__ void k_gemm128_mma(const float* __restrict__ b, int which) {
    extern __shared__ __half sm[];
    __half* Ahi = sm;                        // [64][SA]
    __half* Alo = sm + 64 * SA;              // [64][SA]
    __half* Bhi = sm + 128 * SA;             // [128][SA]  Bhi[n][k]
    __half* Blo = sm + 256 * SA;             // [128][SA]
    float*  bs  = (float*)(sm + 384 * SA);
    int tid = threadIdx.x;
    int wid = tid >> 5, lane = tid & 31;
    int row0 = blockIdx.x * 64;

    // stage A tile (fp32 rows from g_h0 -> hi/lo fp16), zero-pad OOB rows
    for (int idx = tid; idx < 64 * 32; idx += 256) {
        int r = idx >> 5, q = idx & 31;
        float4 v = make_float4(0.f, 0.f, 0.f, 0.f);
        int row = row0 + r;
        if (row < N_NODES) v = ((const float4*)(g_h0 + (size_t)row * HID))[q];
        __half hx = __float2half_rn(v.x), hy = __float2half_rn(v.y);
        __half hz = __float2half_rn(v.z), hw = __float2half_rn(v.w);
        __half lx = __float2half_rn(v.x - __half2float(hx));
        __half ly = __float2half_rn(v.y - __half2float(hy));
        __half lz = __float2half_rn(v.z - __half2float(hz));
        __half lw = __float2half_rn(v.w - __half2float(hw));
        uint2 ph, pl;
        ph.x = h2_as_u32(__halves2half2(hx, hy));
        ph.y = h2_as_u32(__halves2half2(hz, hw));
        pl.x = h2_as_u32(__halves2half2(lx, ly));
        pl.y = h2_as_u32(__halves2half2(lz, lw));
        *(uint2*)(Ahi + r * SA + q * 4) = ph;
        *(uint2*)(Alo + r * SA + q * 4) = pl;
    }
    // stage B from precomputed hi/lo [n][k] (uint4 copies, coalesced)
    {
        const __half* whi = g_whi[which];
        const __half* wlo = g_wlo[which];
        for (int idx = tid; idx < 128 * 16; idx += 256) {
            int n = idx >> 4, seg = idx & 15;
            *(uint4*)(Bhi + n * SA + seg * 8) = *(const uint4*)(whi + n * HID + seg * 8);
            *(uint4*)(Blo + n * SA + seg * 8) = *(const uint4*)(wlo + n * HID + seg * 8);
        }
    }
    if (tid < 128) bs[tid] = __ldg(&b[tid]);
    __syncthreads();

    uint32_t ahi_base = smem_u32(Ahi), alo_base = smem_u32(Alo);
    uint32_t bhi_base = smem_u32(Bhi), blo_base = smem_u32(Blo);
    int R0 = (wid >> 1) * 16;          // row group (0..3)*16
    int NH = (wid & 1) * 64;           // N half

    float d[8][4];
    #pragma unroll
    for (int nt = 0; nt < 8; nt++)
        #pragma unroll
        for (int q = 0; q < 4; q++) d[nt][q] = 0.f;

    #pragma unroll
    for (int kt = 0; kt < 8; kt++) {
        int k0 = kt * 16;
        uint32_t aoff =
            ((uint32_t)((R0 + (lane & 15)) * SA + k0 + ((lane >> 4) << 3)) << 1);
        uint32_t ah0, ah1, ah2, ah3, al0, al1, al2, al3;
        asm volatile("ldmatrix.sync.aligned.m8n8.x4.shared.b16 {%0,%1,%2,%3}, [%4];"
                     : "=r"(ah0), "=r"(ah1), "=r"(ah2), "=r"(ah3) : "r"(ahi_base + aoff));
        asm volatile("ldmatrix.sync.aligned.m8n8.x4.shared.b16 {%0,%1,%2,%3}, [%4];"
                     : "=r"(al0), "=r"(al1), "=r"(al2), "=r"(al3) : "r"(alo_base + aoff));
        #pragma unroll
        for (int nt = 0; nt < 8; nt++) {
            int n0 = NH + nt * 8;
            uint32_t boff =
                ((uint32_t)((n0 + (lane & 7)) * SA + k0 + (lane & 8)) << 1);
            uint32_t bh0, bh1, bl0, bl1;
            asm volatile("ldmatrix.sync.aligned.m8n8.x2.shared.b16 {%0,%1}, [%2];"
                         : "=r"(bh0), "=r"(bh1) : "r"(bhi_base + boff));
            asm volatile("ldmatrix.sync.aligned.m8n8.x2.shared.b16 {%0,%1}, [%2];"
                         : "=r"(bl0), "=r"(bl1) : "r"(blo_base + boff));
            asm volatile(
                "mma.sync.aligned.m16n8k16.row.col.f32.f16.f16.f32 "
                "{%0,%1,%2,%3}, {%4,%5,%6,%7}, {%8,%9}, {%0,%1,%2,%3};"
                : "+f"(d[nt][0]), "+f"(d[nt][1]), "+f"(d[nt][2]), "+f"(d[nt][3])
                : "r"(ah0), "r"(ah1), "r"(ah2), "r"(ah3), "r"(bh0), "r"(bh1));
            asm volatile(
                "mma.sync.aligned.m16n8k16.row.col.f32.f16.f16.f32 "
                "{%0,%1,%2,%3}, {%4,%5,%6,%7}, {%8,%9}, {%0,%1,%2,%3};"
                : "+f"(d[nt][0]), "+f"(d[nt][1]), "+f"(d[nt][2]), "+f"(d[nt][3])
                : "r"(ah0), "r"(ah1), "r"(ah2), "r"(ah3), "r"(bl0), "r"(bl1));
            asm volatile(
                "mma.sync.aligned.m16n8k16.row.col.f32.f16.f16.f32 "
                "{%0,%1,%2,%3}, {%4,%5,%6,%7}, {%8,%9}, {%0,%1,%2,%3};"
                : "+f"(d[nt][0]), "+f"(d[nt][1]), "+f"(d[nt][2]), "+f"(d[nt][3])
                : "r"(al0), "r"(al1), "r"(al2), "r"(al3), "r"(bh0), "r"(bh1));
        }
    }

    // epilogue: bias + relu + fp16 pack
    int rA = row0 + R0 + (lane >> 2);
    int rB = rA + 8;
    int cl = (lane & 3) * 2;
    #pragma unroll
    for (int nt = 0; nt < 8; nt++) {
        int n0 = NH + nt * 8 + cl;
        float bb0 = bs[n0], bb1 = bs[n0 + 1];
        if (rA < N_NODES) {
            __half2 h = __floats2half2_rn(fmaxf(d[nt][0] + bb0, 0.f),
                                          fmaxf(d[nt][1] + bb1, 0.f));
            *(__half2*)(g_h1h + (size_t)rA * HID + n0) = h;
        }
        if (rB < N_NODES) {
            __half2 h = __floats2half2_rn(fmaxf(d[nt][2] + bb0, 0.f),
                                          fmaxf(d[nt][3] + bb1, 0.f));
            *(__half2*)(g_h1h + (size_t)rB * HID + n0) = h;
        }
    }
}

// ---------------- 128-dim aggregation: gathers fp16 g_h1h, writes fp32 g_h0
__global__ void k_aggregate() {
    int node = blockIdx.x * (blockDim.x >> 5) + (threadIdx.x >> 5);
    if (node >= N_NODES) return;
    int lane = threadIdx.x & 31;
    float dd = g_dis[node];
    float s0 = dd * dd;
    uint2 pv = ((const uint2*)(g_h1h + (size_t)node * HID))[lane];
    float2 v0 = __half22float2(u32_as_h2(pv.x));
    float2 v1 = __half22float2(u32_as_h2(pv.y));
    float ax = v0.x * s0, ay = v0.y * s0, az = v1.x * s0, aw = v1.y * s0;
    int beg = real_off(node), end = real_off(node + 1);
    for (int e = beg; e < end; e++) {
        int s = g_srcs[e];
        float w = g_dis[s] * dd;
        uint2 ph = ((const uint2*)(g_h1h + (size_t)s * HID))[lane];
        float2 h0 = __half22float2(u32_as_h2(ph.x));
        float2 h1 = __half22float2(u32_as_h2(ph.y));
        ax += h0.x * w;
        ay += h0.y * w;
        az += h1.x * w;
        aw += h1.y * w;
    }
    ((float4*)(g_h0 + (size_t)node * HID))[lane] = make_float4(ax, ay, az, aw);
}

// ---------------- fused pool + fc1 + fc2 ----------------
__global__ void k_pool_fc(const float* __restrict__ fc1_w, const float* __restrict__ fc1_b,
                          const float* __restrict__ fc2_w, const float* __restrict__ fc2_b,
                          float* __restrict__ out) {
    __shared__ float pooled[HID];
    __shared__ float z[64];
    int g = blockIdx.x, c = threadIdx.x;
    int s = g_gstart[g], e = g_gstart[g + 1];
    float acc = 0.f;
    for (int i = s; i < e; i++) acc += __half2float(g_h1h[(size_t)i * HID + c]);
    float cnt = (float)((e - s) > 1 ? (e - s) : 1);
    pooled[c] = acc / cnt;
    __syncthreads();
    if (c < 64) {
        float a = fc1_b[c];
        #pragma unroll 8
        for (int k = 0; k < HID; k++) a += pooled[k] * fc1_w[k * 64 + c];
        z[c] = fmaxf(a, 0.f);
    }
    __syncthreads();
    if (c == 0) {
        float a = fc2_b[0];
        #pragma unroll 8
        for (int j = 0; j < 64; j++) a += z[j] * fc2_w[j];
        out[g] = a;
    }
}

// ---------------- launch ----------------
extern "C" void kernel_launch(void* const* d_in, const int* in_sizes, int n_in,
                              void* d_out, int out_size) {
    const float* x     = (const float*)d_in[0];
    const int*   ei    = (const int*)d_in[1];   // int64 narrowed to int32 by harness
    const int*   batch = (const int*)d_in[2];
    const float* W1 = (const float*)d_in[3];
    const float* b1 = (const float*)d_in[4];
    const float* W2 = (const float*)d_in[5];
    const float* b2 = (const float*)d_in[6];
    const float* W3 = (const float*)d_in[7];
    const float* b3 = (const float*)d_in[8];
    const float* fc1_w = (const float*)d_in[9];
    const float* fc1_b = (const float*)d_in[10];
    const float* fc2_w = (const float*)d_in[11];
    const float* fc2_b = (const float*)d_in[12];
    float* out = (float*)d_out;

    cudaFuncSetAttribute(k_gemm128_mma,
                         cudaFuncAttributeMaxDynamicSharedMemorySize, SMEM_MMA_BYTES);

    k_init_wsplit<<<256, 256>>>(W2, W3);
    k_degree<<<(N_EDGES + 255) / 256, 256>>>(ei);
    k_scan1<<<SCAN_NB, 256>>>(batch);
    k_scan2<<<1, 256>>>();
    k_fill<<<(N_EDGES + 255) / 256, 256>>>(ei);

    const int AGG_BLOCKS = (N_NODES + 7) / 8;
    const int TC_BLOCKS = (N_NODES + 63) / 64;     // 782

    // layer 1 (fused agg + 6x128 gemm)
    k_aggx_gemm6<<<(N_NODES + 255) / 256, 256>>>(x, W1, b1);
    // layer 2
    k_aggregate<<<AGG_BLOCKS, 256>>>();
    k_gemm128_mma<<<TC_BLOCKS, 256, SMEM_MMA_BYTES>>>(b2, 0);
    // layer 3
    k_aggregate<<<AGG_BLOCKS, 256>>>();
    k_gemm128_mma<<<TC_BLOCKS, 256, SMEM_MMA_BYTES>>>(b3, 1);

    // fused pool + MLP
    k_pool_fc<<<N_GRAPHS, HID>>>(fc1_w, fc1_b, fc2_w, fc2_b, out);
}

// round 16
// speedup vs baseline: 1.6057x; 1.0629x over previous
#include <cuda_runtime.h>
#include <cuda_fp16.h>
#include <cuda_bf16.h>
#include <cstdint>

#define N_NODES 50000
#define N_EDGES 600000
#define N_GRAPHS 64
#define HID 128
#define SCAN_NB ((N_NODES + 255) / 256)   // 196
#define GEMM_CTAS 296                      // 2 per SM x 148

__device__ __forceinline__ unsigned int h2_as_u32(__half2 h) {
    return *reinterpret_cast<unsigned int*>(&h);
}
__device__ __forceinline__ __half2 u32_as_h2(unsigned int u) {
    return *reinterpret_cast<__half2*>(&u);
}
__device__ __forceinline__ uint32_t smem_u32(const void* p) {
    uint32_t a;
    asm("{ .reg .u64 t; cvta.to.shared.u64 t, %1; cvt.u32.u64 %0, t; }" : "=r"(a) : "l"(p));
    return a;
}

// ---------------- scratch (static device globals; no allocation) ----------------
__device__ int    g_indeg[N_NODES];
__device__ float  g_dis[N_NODES];
__device__ int    g_offs[N_NODES + 1];
__device__ int    g_fill[N_NODES];
__device__ int    g_srcs[N_EDGES];
__device__ int    g_bsum[256];
__device__ float  g_h0[(size_t)N_NODES * HID];   // agg output (fp32, GEMM A operand)
__device__ __half g_h1h[(size_t)N_NODES * HID];  // GEMM output (fp16, gathered)
__device__ int    g_gstart[N_GRAPHS + 1];
// precomputed W^T hi/lo fp16 [n][k]: index 0 = W2, 1 = W3
__device__ __half g_whi[2][HID * HID];
__device__ __half g_wlo[2][HID * HID];

__device__ __forceinline__ int real_off(int i) { return g_offs[i] + g_bsum[i >> 8]; }

// ---------------- init (zero counters) + W2/W3 hi/lo split, fused ----------------
__global__ void k_init_wsplit(const float* __restrict__ W2, const float* __restrict__ W3) {
    int gidx = blockIdx.x * blockDim.x + threadIdx.x;
    for (int i = gidx; i < N_NODES; i += gridDim.x * blockDim.x) {
        g_indeg[i] = 0;
        g_fill[i] = 0;
    }
    if (gidx < 2 * HID * HID) {
        int m = gidx >> 14;                     // 0: W2, 1: W3
        int e = gidx & 16383;
        int k = e >> 7, n = e & 127;
        const float* W = m ? W3 : W2;
        float w = __ldg(&W[e]);
        __half hi = __float2half_rn(w);
        __half lo = __float2half_rn(w - __half2float(hi));
        g_whi[m][n * HID + k] = hi;
        g_wlo[m][n * HID + k] = lo;
    }
}

__global__ void k_degree(const int* __restrict__ ei) {
    int i = blockIdx.x * blockDim.x + threadIdx.x;
    if (i >= N_EDGES) return;
    int d = ei[N_EDGES + i];
    if (d >= 0 && d < N_NODES) atomicAdd(&g_indeg[d], 1);
}

__global__ void k_scan1(const int* __restrict__ batch) {
    __shared__ int wsum[8];
    int tid = threadIdx.x, lane = tid & 31, wid = tid >> 5;
    int i = blockIdx.x * 256 + tid;
    int v = (i < N_NODES) ? g_indeg[i] : 0;
    if (i < N_NODES) g_dis[i] = rsqrtf((float)(v + 1));
    int s = v;
    #pragma unroll
    for (int o = 1; o < 32; o <<= 1) {
        int t = __shfl_up_sync(0xffffffffu, s, o);
        if (lane >= o) s += t;
    }
    if (lane == 31) wsum[wid] = s;
    __syncthreads();
    if (tid == 0) {
        int run = 0;
        #pragma unroll
        for (int j = 0; j < 8; j++) { int t = wsum[j]; wsum[j] = run; run += t; }
        g_bsum[blockIdx.x] = run;
    }
    __syncthreads();
    int excl = wsum[wid] + (s - v);
    if (i <= N_NODES) g_offs[i] = excl;

    if (i < N_NODES) {
        int b = batch[i];
        if (b < 0) b = 0;
        if (b >= N_GRAPHS) b = N_GRAPHS - 1;
        int prev;
        if (i == 0) prev = -1;
        else {
            prev = batch[i - 1];
            if (prev < 0) prev = 0;
            if (prev >= N_GRAPHS) prev = N_GRAPHS - 1;
        }
        for (int g = prev + 1; g <= b; g++) g_gstart[g] = i;
        if (i == N_NODES - 1)
            for (int g = b + 1; g <= N_GRAPHS; g++) g_gstart[g] = N_NODES;
    }
}

__global__ void k_scan2() {
    __shared__ int wsum[8];
    int tid = threadIdx.x, lane = tid & 31, wid = tid >> 5;
    int v = (tid < SCAN_NB) ? g_bsum[tid] : 0;
    int s = v;
    #pragma unroll
    for (int o = 1; o < 32; o <<= 1) {
        int t = __shfl_up_sync(0xffffffffu, s, o);
        if (lane >= o) s += t;
    }
    if (lane == 31) wsum[wid] = s;
    __syncthreads();
    if (tid == 0) {
        int run = 0;
        #pragma unroll
        for (int j = 0; j < 8; j++) { int t = wsum[j]; wsum[j] = run; run += t; }
    }
    __syncthreads();
    int excl = wsum[wid] + (s - v);
    if (tid < SCAN_NB) g_bsum[tid] = excl;
}

__global__ void k_fill(const int* __restrict__ ei) {
    int i = blockIdx.x * blockDim.x + threadIdx.x;
    if (i >= N_EDGES) return;
    int s = ei[i];
    int d = ei[N_EDGES + i];
    if (s < 0 || s >= N_NODES || d < 0 || d >= N_NODES) return;
    int pos = real_off(d) + atomicAdd(&g_fill[d], 1);
    g_srcs[pos] = s;
}

// ---------------- fused layer 1: agg(x)[6] then @W1[6,128]+b1, relu -> g_h1h
__global__ void k_aggx_gemm6(const float* __restrict__ x,
                             const float* __restrict__ W,
                             const float* __restrict__ b) {
    __shared__ float Asm[256][6];
    int tid = threadIdx.x;
    int node = blockIdx.x * 256 + tid;

    if (node < N_NODES) {
        float dd = g_dis[node];
        float s0 = dd * dd;
        const float2* xr = (const float2*)(x + node * 6);
        float2 a0 = xr[0], a1 = xr[1], a2 = xr[2];
        a0.x *= s0; a0.y *= s0; a1.x *= s0; a1.y *= s0; a2.x *= s0; a2.y *= s0;
        int beg = real_off(node), end = real_off(node + 1);
        for (int e = beg; e < end; e++) {
            int s = g_srcs[e];
            float w = g_dis[s] * dd;
            const float2* xs = (const float2*)(x + s * 6);
            float2 v0 = xs[0], v1 = xs[1], v2 = xs[2];
            a0.x += v0.x * w; a0.y += v0.y * w;
            a1.x += v1.x * w; a1.y += v1.y * w;
            a2.x += v2.x * w; a2.y += v2.y * w;
        }
        Asm[tid][0] = a0.x; Asm[tid][1] = a0.y;
        Asm[tid][2] = a1.x; Asm[tid][3] = a1.y;
        Asm[tid][4] = a2.x; Asm[tid][5] = a2.y;
    }
    __syncthreads();

    int j = tid & 63;
    int c0 = j * 2;
    float w0[6], w1[6];
    #pragma unroll
    for (int k = 0; k < 6; k++) {
        w0[k] = __ldg(&W[k * HID + c0]);
        w1[k] = __ldg(&W[k * HID + c0 + 1]);
    }
    float bb0 = __ldg(&b[c0]), bb1 = __ldg(&b[c0 + 1]);
    int nbase = blockIdx.x * 256;
    for (int r = tid >> 6; r < 256; r += 4) {
        int row = nbase + r;
        if (row >= N_NODES) break;
        float acc0 = bb0, acc1 = bb1;
        #pragma unroll
        for (int k = 0; k < 6; k++) {
            float a = Asm[r][k];
            acc0 += a * w0[k];
            acc1 += a * w1[k];
        }
        __half2 h = __floats2half2_rn(fmaxf(acc0, 0.f), fmaxf(acc1, 0.f));
        ((__half2*)(g_h1h + (size_t)row * HID))[j] = h;
    }
}

// ---------------- split-fp16 HMMA GEMM (persistent CTAs): B staged once,
// loop over 64-row tiles. 8 warps = 4 row-groups x 2 N-halves.
#define SA 136                                          // padded row stride (halfs)
#define SMEM_MMA_BYTES ((64 + 64 + 128 + 128) * SA * 2 + 512)
__global__ void k_gemm128_mma(const float* __restrict__ b, int which) {
    extern __shared__ __half sm[];
    __half* Ahi = sm;                        // [64][SA]
    __half* Alo = sm + 64 * SA;              // [64][SA]
    __half* Bhi = sm + 128 * SA;             // [128][SA]  Bhi[n][k]
    __half* Blo = sm + 256 * SA;             // [128][SA]
    float*  bs  = (float*)(sm + 384 * SA);
    int tid = threadIdx.x;
    int wid = tid >> 5, lane = tid & 31;

    // stage B + bias ONCE per CTA
    {
        const __half* whi = g_whi[which];
        const __half* wlo = g_wlo[which];
        for (int idx = tid; idx < 128 * 16; idx += 256) {
            int n = idx >> 4, seg = idx & 15;
            *(uint4*)(Bhi + n * SA + seg * 8) = *(const uint4*)(whi + n * HID + seg * 8);
            *(uint4*)(Blo + n * SA + seg * 8) = *(const uint4*)(wlo + n * HID + seg * 8);
        }
        if (tid < 128) bs[tid] = __ldg(&b[tid]);
    }

    uint32_t ahi_base = smem_u32(Ahi), alo_base = smem_u32(Alo);
    uint32_t bhi_base = smem_u32(Bhi), blo_base = smem_u32(Blo);
    int R0 = (wid >> 1) * 16;          // row group (0..3)*16
    int NH = (wid & 1) * 64;           // N half

    for (int tile = blockIdx.x; tile * 64 < N_NODES; tile += GEMM_CTAS) {
        int row0 = tile * 64;
        __syncthreads();   // prior tile's ldmatrix done (and B staged, 1st iter)

        // stage A tile (fp32 -> hi/lo fp16), zero-pad OOB rows
        for (int idx = tid; idx < 64 * 32; idx += 256) {
            int r = idx >> 5, q = idx & 31;
            float4 v = make_float4(0.f, 0.f, 0.f, 0.f);
            int row = row0 + r;
            if (row < N_NODES) v = ((const float4*)(g_h0 + (size_t)row * HID))[q];
            __half hx = __float2half_rn(v.x), hy = __float2half_rn(v.y);
            __half hz = __float2half_rn(v.z), hw = __float2half_rn(v.w);
            __half lx = __float2half_rn(v.x - __half2float(hx));
            __half ly = __float2half_rn(v.y - __half2float(hy));
            __half lz = __float2half_rn(v.z - __half2float(hz));
            __half lw = __float2half_rn(v.w - __half2float(hw));
            uint2 ph, pl;
            ph.x = h2_as_u32(__halves2half2(hx, hy));
            ph.y = h2_as_u32(__halves2half2(hz, hw));
            pl.x = h2_as_u32(__halves2half2(lx, ly));
            pl.y = h2_as_u32(__halves2half2(lz, lw));
            *(uint2*)(Ahi + r * SA + q * 4) = ph;
            *(uint2*)(Alo + r * SA + q * 4) = pl;
        }
        __syncthreads();

        float d[8][4];
        #pragma unroll
        for (int nt = 0; nt < 8; nt++)
            #pragma unroll
            for (int q = 0; q < 4; q++) d[nt][q] = 0.f;

        #pragma unroll
        for (int kt = 0; kt < 8; kt++) {
            int k0 = kt * 16;
            uint32_t aoff =
                ((uint32_t)((R0 + (lane & 15)) * SA + k0 + ((lane >> 4) << 3)) << 1);
            uint32_t ah0, ah1, ah2, ah3, al0, al1, al2, al3;
            asm volatile("ldmatrix.sync.aligned.m8n8.x4.shared.b16 {%0,%1,%2,%3}, [%4];"
                         : "=r"(ah0), "=r"(ah1), "=r"(ah2), "=r"(ah3) : "r"(ahi_base + aoff));
            asm volatile("ldmatrix.sync.aligned.m8n8.x4.shared.b16 {%0,%1,%2,%3}, [%4];"
                         : "=r"(al0), "=r"(al1), "=r"(al2), "=r"(al3) : "r"(alo_base + aoff));
            #pragma unroll
            for (int nt = 0; nt < 8; nt++) {
                int n0 = NH + nt * 8;
                uint32_t boff =
                    ((uint32_t)((n0 + (lane & 7)) * SA + k0 + (lane & 8)) << 1);
                uint32_t bh0, bh1, bl0, bl1;
                asm volatile("ldmatrix.sync.aligned.m8n8.x2.shared.b16 {%0,%1}, [%2];"
                             : "=r"(bh0), "=r"(bh1) : "r"(bhi_base + boff));
                asm volatile("ldmatrix.sync.aligned.m8n8.x2.shared.b16 {%0,%1}, [%2];"
                             : "=r"(bl0), "=r"(bl1) : "r"(blo_base + boff));
                asm volatile(
                    "mma.sync.aligned.m16n8k16.row.col.f32.f16.f16.f32 "
                    "{%0,%1,%2,%3}, {%4,%5,%6,%7}, {%8,%9}, {%0,%1,%2,%3};"
                    : "+f"(d[nt][0]), "+f"(d[nt][1]), "+f"(d[nt][2]), "+f"(d[nt][3])
                    : "r"(ah0), "r"(ah1), "r"(ah2), "r"(ah3), "r"(bh0), "r"(bh1));
                asm volatile(
                    "mma.sync.aligned.m16n8k16.row.col.f32.f16.f16.f32 "
                    "{%0,%1,%2,%3}, {%4,%5,%6,%7}, {%8,%9}, {%0,%1,%2,%3};"
                    : "+f"(d[nt][0]), "+f"(d[nt][1]), "+f"(d[nt][2]), "+f"(d[nt][3])
                    : "r"(ah0), "r"(ah1), "r"(ah2), "r"(ah3), "r"(bl0), "r"(bl1));
                asm volatile(
                    "mma.sync.aligned.m16n8k16.row.col.f32.f16.f16.f32 "
                    "{%0,%1,%2,%3}, {%4,%5,%6,%7}, {%8,%9}, {%0,%1,%2,%3};"
                    : "+f"(d[nt][0]), "+f"(d[nt][1]), "+f"(d[nt][2]), "+f"(d[nt][3])
                    : "r"(al0), "r"(al1), "r"(al2), "r"(al3), "r"(bh0), "r"(bh1));
            }
        }

        // epilogue: bias + relu + fp16 pack
        int rA = row0 + R0 + (lane >> 2);
        int rB = rA + 8;
        int cl = (lane & 3) * 2;
        #pragma unroll
        for (int nt = 0; nt < 8; nt++) {
            int n0 = NH + nt * 8 + cl;
            float bb0 = bs[n0], bb1 = bs[n0 + 1];
            if (rA < N_NODES) {
                __half2 h = __floats2half2_rn(fmaxf(d[nt][0] + bb0, 0.f),
                                              fmaxf(d[nt][1] + bb1, 0.f));
                *(__half2*)(g_h1h + (size_t)rA * HID + n0) = h;
            }
            if (rB < N_NODES) {
                __half2 h = __floats2half2_rn(fmaxf(d[nt][2] + bb0, 0.f),
                                              fmaxf(d[nt][3] + bb1, 0.f));
                *(__half2*)(g_h1h + (size_t)rB * HID + n0) = h;
            }
        }
    }
}

// ---------------- 128-dim aggregation: gathers fp16 g_h1h, writes fp32 g_h0
__global__ void k_aggregate() {
    int node = blockIdx.x * (blockDim.x >> 5) + (threadIdx.x >> 5);
    if (node >= N_NODES) return;
    int lane = threadIdx.x & 31;
    float dd = g_dis[node];
    float s0 = dd * dd;
    uint2 pv = ((const uint2*)(g_h1h + (size_t)node * HID))[lane];
    float2 v0 = __half22float2(u32_as_h2(pv.x));
    float2 v1 = __half22float2(u32_as_h2(pv.y));
    float ax = v0.x * s0, ay = v0.y * s0, az = v1.x * s0, aw = v1.y * s0;
    int beg = real_off(node), end = real_off(node + 1);
    for (int e = beg; e < end; e++) {
        int s = g_srcs[e];
        float w = g_dis[s] * dd;
        uint2 ph = ((const uint2*)(g_h1h + (size_t)s * HID))[lane];
        float2 h0 = __half22float2(u32_as_h2(ph.x));
        float2 h1 = __half22float2(u32_as_h2(ph.y));
        ax += h0.x * w;
        ay += h0.y * w;
        az += h1.x * w;
        aw += h1.y * w;
    }
    ((float4*)(g_h0 + (size_t)node * HID))[lane] = make_float4(ax, ay, az, aw);
}

// ---------------- fused pool + fc1 + fc2 ----------------
__global__ void k_pool_fc(const float* __restrict__ fc1_w, const float* __restrict__ fc1_b,
                          const float* __restrict__ fc2_w, const float* __restrict__ fc2_b,
                          float* __restrict__ out) {
    __shared__ float pooled[HID];
    __shared__ float z[64];
    int g = blockIdx.x, c = threadIdx.x;
    int s = g_gstart[g], e = g_gstart[g + 1];
    float acc = 0.f;
    for (int i = s; i < e; i++) acc += __half2float(g_h1h[(size_t)i * HID + c]);
    float cnt = (float)((e - s) > 1 ? (e - s) : 1);
    pooled[c] = acc / cnt;
    __syncthreads();
    if (c < 64) {
        float a = fc1_b[c];
        #pragma unroll 8
        for (int k = 0; k < HID; k++) a += pooled[k] * fc1_w[k * 64 + c];
        z[c] = fmaxf(a, 0.f);
    }
    __syncthreads();
    if (c == 0) {
        float a = fc2_b[0];
        #pragma unroll 8
        for (int j = 0; j < 64; j++) a += z[j] * fc2_w[j];
        out[g] = a;
    }
}

// ---------------- launch ----------------
extern "C" void kernel_launch(void* const* d_in, const int* in_sizes, int n_in,
                              void* d_out, int out_size) {
    const float* x     = (const float*)d_in[0];
    const int*   ei    = (const int*)d_in[1];   // int64 narrowed to int32 by harness
    const int*   batch = (const int*)d_in[2];
    const float* W1 = (const float*)d_in[3];
    const float* b1 = (const float*)d_in[4];
    const float* W2 = (const float*)d_in[5];
    const float* b2 = (const float*)d_in[6];
    const float* W3 = (const float*)d_in[7];
    const float* b3 = (const float*)d_in[8];
    const float* fc1_w = (const float*)d_in[9];
    const float* fc1_b = (const float*)d_in[10];
    const float* fc2_w = (const float*)d_in[11];
    const float* fc2_b = (const float*)d_in[12];
    float* out = (float*)d_out;

    cudaFuncSetAttribute(k_gemm128_mma,
                         cudaFuncAttributeMaxDynamicSharedMemorySize, SMEM_MMA_BYTES);

    k_init_wsplit<<<256, 256>>>(W2, W3);
    k_degree<<<(N_EDGES + 255) / 256, 256>>>(ei);
    k_scan1<<<SCAN_NB, 256>>>(batch);
    k_scan2<<<1, 256>>>();
    k_fill<<<(N_EDGES + 255) / 256, 256>>>(ei);

    const int AGG_BLOCKS = (N_NODES + 7) / 8;

    // layer 1 (fused agg + 6x128 gemm)
    k_aggx_gemm6<<<(N_NODES + 255) / 256, 256>>>(x, W1, b1);
    // layer 2
    k_aggregate<<<AGG_BLOCKS, 256>>>();
    k_gemm128_mma<<<GEMM_CTAS, 256, SMEM_MMA_BYTES>>>(b2, 0);
    // layer 3
    k_aggregate<<<AGG_BLOCKS, 256>>>();
    k_gemm128_mma<<<GEMM_CTAS, 256, SMEM_MMA_BYTES>>>(b3, 1);

    // fused pool + MLP
    k_pool_fc<<<N_GRAPHS, HID>>>(fc1_w, fc1_b, fc2_w, fc2_b, out);
}

// round 17
// speedup vs baseline: 1.6262x; 1.0128x over previous
#include <cuda_runtime.h>
#include <cuda_fp16.h>
#include <cuda_bf16.h>
#include <cstdint>

#define N_NODES 50000
#define N_EDGES 600000
#define N_GRAPHS 64
#define HID 128
#define SCAN_NB ((N_NODES + 255) / 256)   // 196
#define GEMM_CTAS 296                      // 2 per SM x 148

__device__ __forceinline__ unsigned int h2_as_u32(__half2 h) {
    return *reinterpret_cast<unsigned int*>(&h);
}
__device__ __forceinline__ __half2 u32_as_h2(unsigned int u) {
    return *reinterpret_cast<__half2*>(&u);
}
__device__ __forceinline__ uint32_t smem_u32(const void* p) {
    uint32_t a;
    asm("{ .reg .u64 t; cvta.to.shared.u64 t, %1; cvt.u32.u64 %0, t; }" : "=r"(a) : "l"(p));
    return a;
}

// ---------------- scratch (static device globals; no allocation) ----------------
// NOTE: counters (g_indeg, g_fill) are zero at module load and are re-zeroed at the
// tail of k_aggx_gemm6 every call, so each graph replay starts from the same state.
__device__ int    g_indeg[N_NODES];
__device__ float  g_dis[N_NODES];
__device__ int    g_offs[N_NODES + 1];
__device__ int    g_fill[N_NODES];
__device__ int    g_srcs[N_EDGES];
__device__ int    g_bsum[256];
__device__ float  g_h0[(size_t)N_NODES * HID];   // agg output (fp32, GEMM A operand)
__device__ __half g_h1h[(size_t)N_NODES * HID];  // GEMM output (fp16, gathered)
__device__ int    g_gstart[N_GRAPHS + 1];
// precomputed W^T hi/lo fp16 [n][k]: index 0 = W2, 1 = W3
__device__ __half g_whi[2][HID * HID];
__device__ __half g_wlo[2][HID * HID];

__device__ __forceinline__ int real_off(int i) { return g_offs[i] + g_bsum[i >> 8]; }

__global__ void k_degree(const int* __restrict__ ei) {
    int i = blockIdx.x * blockDim.x + threadIdx.x;
    if (i >= N_EDGES) return;
    int d = ei[N_EDGES + i];
    if (d >= 0 && d < N_NODES) atomicAdd(&g_indeg[d], 1);
}

// scan level 1 + g_dis + graph bounds + W2/W3 hi/lo split (fused)
__global__ void k_scan1(const int* __restrict__ batch,
                        const float* __restrict__ W2, const float* __restrict__ W3) {
    __shared__ int wsum[8];
    int tid = threadIdx.x, lane = tid & 31, wid = tid >> 5;
    int i = blockIdx.x * 256 + tid;
    int v = (i < N_NODES) ? g_indeg[i] : 0;
    if (i < N_NODES) g_dis[i] = rsqrtf((float)(v + 1));
    int s = v;
    #pragma unroll
    for (int o = 1; o < 32; o <<= 1) {
        int t = __shfl_up_sync(0xffffffffu, s, o);
        if (lane >= o) s += t;
    }
    if (lane == 31) wsum[wid] = s;
    __syncthreads();
    if (tid == 0) {
        int run = 0;
        #pragma unroll
        for (int j = 0; j < 8; j++) { int t = wsum[j]; wsum[j] = run; run += t; }
        g_bsum[blockIdx.x] = run;
    }
    __syncthreads();
    int excl = wsum[wid] + (s - v);
    if (i <= N_NODES) g_offs[i] = excl;

    if (i < N_NODES) {
        int b = batch[i];
        if (b < 0) b = 0;
        if (b >= N_GRAPHS) b = N_GRAPHS - 1;
        int prev;
        if (i == 0) prev = -1;
        else {
            prev = batch[i - 1];
            if (prev < 0) prev = 0;
            if (prev >= N_GRAPHS) prev = N_GRAPHS - 1;
        }
        for (int g = prev + 1; g <= b; g++) g_gstart[g] = i;
        if (i == N_NODES - 1)
            for (int g = b + 1; g <= N_GRAPHS; g++) g_gstart[g] = N_NODES;
    }

    // fused: W split (independent of counters)
    if (i < 2 * HID * HID) {
        int m = i >> 14;                        // 0: W2, 1: W3
        int e = i & 16383;
        int k = e >> 7, n = e & 127;
        const float* W = m ? W3 : W2;
        float w = __ldg(&W[e]);
        __half hi = __float2half_rn(w);
        __half lo = __float2half_rn(w - __half2float(hi));
        g_whi[m][n * HID + k] = hi;
        g_wlo[m][n * HID + k] = lo;
    }
}

__global__ void k_scan2() {
    __shared__ int wsum[8];
    int tid = threadIdx.x, lane = tid & 31, wid = tid >> 5;
    int v = (tid < SCAN_NB) ? g_bsum[tid] : 0;
    int s = v;
    #pragma unroll
    for (int o = 1; o < 32; o <<= 1) {
        int t = __shfl_up_sync(0xffffffffu, s, o);
        if (lane >= o) s += t;
    }
    if (lane == 31) wsum[wid] = s;
    __syncthreads();
    if (tid == 0) {
        int run = 0;
        #pragma unroll
        for (int j = 0; j < 8; j++) { int t = wsum[j]; wsum[j] = run; run += t; }
    }
    __syncthreads();
    int excl = wsum[wid] + (s - v);
    if (tid < SCAN_NB) g_bsum[tid] = excl;
}

__global__ void k_fill(const int* __restrict__ ei) {
    int i = blockIdx.x * blockDim.x + threadIdx.x;
    if (i >= N_EDGES) return;
    int s = ei[i];
    int d = ei[N_EDGES + i];
    if (s < 0 || s >= N_NODES || d < 0 || d >= N_NODES) return;
    int pos = real_off(d) + atomicAdd(&g_fill[d], 1);
    g_srcs[pos] = s;
}

// ---------------- fused layer 1: agg(x)[6] then @W1[6,128]+b1, relu -> g_h1h
// Tail: re-zero g_indeg / g_fill for the next replay (counters no longer needed).
__global__ void k_aggx_gemm6(const float* __restrict__ x,
                             const float* __restrict__ W,
                             const float* __restrict__ b) {
    __shared__ float Asm[256][6];
    int tid = threadIdx.x;
    int node = blockIdx.x * 256 + tid;

    if (node < N_NODES) {
        float dd = g_dis[node];
        float s0 = dd * dd;
        const float2* xr = (const float2*)(x + node * 6);
        float2 a0 = xr[0], a1 = xr[1], a2 = xr[2];
        a0.x *= s0; a0.y *= s0; a1.x *= s0; a1.y *= s0; a2.x *= s0; a2.y *= s0;
        int beg = real_off(node), end = real_off(node + 1);
        for (int e = beg; e < end; e++) {
            int s = g_srcs[e];
            float w = g_dis[s] * dd;
            const float2* xs = (const float2*)(x + s * 6);
            float2 v0 = xs[0], v1 = xs[1], v2 = xs[2];
            a0.x += v0.x * w; a0.y += v0.y * w;
            a1.x += v1.x * w; a1.y += v1.y * w;
            a2.x += v2.x * w; a2.y += v2.y * w;
        }
        Asm[tid][0] = a0.x; Asm[tid][1] = a0.y;
        Asm[tid][2] = a1.x; Asm[tid][3] = a1.y;
        Asm[tid][4] = a2.x; Asm[tid][5] = a2.y;
        // re-zero counters for next replay (last consumers already ran)
        g_indeg[node] = 0;
        g_fill[node] = 0;
    }
    __syncthreads();

    int j = tid & 63;
    int c0 = j * 2;
    float w0[6], w1[6];
    #pragma unroll
    for (int k = 0; k < 6; k++) {
        w0[k] = __ldg(&W[k * HID + c0]);
        w1[k] = __ldg(&W[k * HID + c0 + 1]);
    }
    float bb0 = __ldg(&b[c0]), bb1 = __ldg(&b[c0 + 1]);
    int nbase = blockIdx.x * 256;
    for (int r = tid >> 6; r < 256; r += 4) {
        int row = nbase + r;
        if (row >= N_NODES) break;
        float acc0 = bb0, acc1 = bb1;
        #pragma unroll
        for (int k = 0; k < 6; k++) {
            float a = Asm[r][k];
            acc0 += a * w0[k];
            acc1 += a * w1[k];
        }
        __half2 h = __floats2half2_rn(fmaxf(acc0, 0.f), fmaxf(acc1, 0.f));
        ((__half2*)(g_h1h + (size_t)row * HID))[j] = h;
    }
}

// ---------------- split-fp16 HMMA GEMM (persistent CTAs): B staged once,
// loop over 64-row tiles. 8 warps = 4 row-groups x 2 N-halves.
#define SA 136                                          // padded row stride (halfs)
#define SMEM_MMA_BYTES ((64 + 64 + 128 + 128) * SA * 2 + 512)
__global__ void k_gemm128_mma(const float* __restrict__ b, int which) {
    extern __shared__ __half sm[];
    __half* Ahi = sm;                        // [64][SA]
    __half* Alo = sm + 64 * SA;              // [64][SA]
    __half* Bhi = sm + 128 * SA;             // [128][SA]  Bhi[n][k]
    __half* Blo = sm + 256 * SA;             // [128][SA]
    float*  bs  = (float*)(sm + 384 * SA);
    int tid = threadIdx.x;
    int wid = tid >> 5, lane = tid & 31;

    // stage B + bias ONCE per CTA
    {
        const __half* whi = g_whi[which];
        const __half* wlo = g_wlo[which];
        for (int idx = tid; idx < 128 * 16; idx += 256) {
            int n = idx >> 4, seg = idx & 15;
            *(uint4*)(Bhi + n * SA + seg * 8) = *(const uint4*)(whi + n * HID + seg * 8);
            *(uint4*)(Blo + n * SA + seg * 8) = *(const uint4*)(wlo + n * HID + seg * 8);
        }
        if (tid < 128) bs[tid] = __ldg(&b[tid]);
    }

    uint32_t ahi_base = smem_u32(Ahi), alo_base = smem_u32(Alo);
    uint32_t bhi_base = smem_u32(Bhi), blo_base = smem_u32(Blo);
    int R0 = (wid >> 1) * 16;          // row group (0..3)*16
    int NH = (wid & 1) * 64;           // N half

    for (int tile = blockIdx.x; tile * 64 < N_NODES; tile += GEMM_CTAS) {
        int row0 = tile * 64;
        __syncthreads();   // prior tile's ldmatrix done (and B staged, 1st iter)

        // stage A tile (fp32 -> hi/lo fp16), zero-pad OOB rows
        for (int idx = tid; idx < 64 * 32; idx += 256) {
            int r = idx >> 5, q = idx & 31;
            float4 v = make_float4(0.f, 0.f, 0.f, 0.f);
            int row = row0 + r;
            if (row < N_NODES) v = ((const float4*)(g_h0 + (size_t)row * HID))[q];
            __half hx = __float2half_rn(v.x), hy = __float2half_rn(v.y);
            __half hz = __float2half_rn(v.z), hw = __float2half_rn(v.w);
            __half lx = __float2half_rn(v.x - __half2float(hx));
            __half ly = __float2half_rn(v.y - __half2float(hy));
            __half lz = __float2half_rn(v.z - __half2float(hz));
            __half lw = __float2half_rn(v.w - __half2float(hw));
            uint2 ph, pl;
            ph.x = h2_as_u32(__halves2half2(hx, hy));
            ph.y = h2_as_u32(__halves2half2(hz, hw));
            pl.x = h2_as_u32(__halves2half2(lx, ly));
            pl.y = h2_as_u32(__halves2half2(lz, lw));
            *(uint2*)(Ahi + r * SA + q * 4) = ph;
            *(uint2*)(Alo + r * SA + q * 4) = pl;
        }
        __syncthreads();

        float d[8][4];
        #pragma unroll
        for (int nt = 0; nt < 8; nt++)
            #pragma unroll
            for (int q = 0; q < 4; q++) d[nt][q] = 0.f;

        #pragma unroll
        for (int kt = 0; kt < 8; kt++) {
            int k0 = kt * 16;
            uint32_t aoff =
                ((uint32_t)((R0 + (lane & 15)) * SA + k0 + ((lane >> 4) << 3)) << 1);
            uint32_t ah0, ah1, ah2, ah3, al0, al1, al2, al3;
            asm volatile("ldmatrix.sync.aligned.m8n8.x4.shared.b16 {%0,%1,%2,%3}, [%4];"
                         : "=r"(ah0), "=r"(ah1), "=r"(ah2), "=r"(ah3) : "r"(ahi_base + aoff));
            asm volatile("ldmatrix.sync.aligned.m8n8.x4.shared.b16 {%0,%1,%2,%3}, [%4];"
                         : "=r"(al0), "=r"(al1), "=r"(al2), "=r"(al3) : "r"(alo_base + aoff));
            #pragma unroll
            for (int nt = 0; nt < 8; nt++) {
                int n0 = NH + nt * 8;
                uint32_t boff =
                    ((uint32_t)((n0 + (lane & 7)) * SA + k0 + (lane & 8)) << 1);
                uint32_t bh0, bh1, bl0, bl1;
                asm volatile("ldmatrix.sync.aligned.m8n8.x2.shared.b16 {%0,%1}, [%2];"
                             : "=r"(bh0), "=r"(bh1) : "r"(bhi_base + boff));
                asm volatile("ldmatrix.sync.aligned.m8n8.x2.shared.b16 {%0,%1}, [%2];"
                             : "=r"(bl0), "=r"(bl1) : "r"(blo_base + boff));
                asm volatile(
                    "mma.sync.aligned.m16n8k16.row.col.f32.f16.f16.f32 "
                    "{%0,%1,%2,%3}, {%4,%5,%6,%7}, {%8,%9}, {%0,%1,%2,%3};"
                    : "+f"(d[nt][0]), "+f"(d[nt][1]), "+f"(d[nt][2]), "+f"(d[nt][3])
                    : "r"(ah0), "r"(ah1), "r"(ah2), "r"(ah3), "r"(bh0), "r"(bh1));
                asm volatile(
                    "mma.sync.aligned.m16n8k16.row.col.f32.f16.f16.f32 "
                    "{%0,%1,%2,%3}, {%4,%5,%6,%7}, {%8,%9}, {%0,%1,%2,%3};"
                    : "+f"(d[nt][0]), "+f"(d[nt][1]), "+f"(d[nt][2]), "+f"(d[nt][3])
                    : "r"(ah0), "r"(ah1), "r"(ah2), "r"(ah3), "r"(bl0), "r"(bl1));
                asm volatile(
                    "mma.sync.aligned.m16n8k16.row.col.f32.f16.f16.f32 "
                    "{%0,%1,%2,%3}, {%4,%5,%6,%7}, {%8,%9}, {%0,%1,%2,%3};"
                    : "+f"(d[nt][0]), "+f"(d[nt][1]), "+f"(d[nt][2]), "+f"(d[nt][3])
                    : "r"(al0), "r"(al1), "r"(al2), "r"(al3), "r"(bh0), "r"(bh1));
            }
        }

        // epilogue: bias + relu + fp16 pack
        int rA = row0 + R0 + (lane >> 2);
        int rB = rA + 8;
        int cl = (lane & 3) * 2;
        #pragma unroll
        for (int nt = 0; nt < 8; nt++) {
            int n0 = NH + nt * 8 + cl;
            float bb0 = bs[n0], bb1 = bs[n0 + 1];
            if (rA < N_NODES) {
                __half2 h = __floats2half2_rn(fmaxf(d[nt][0] + bb0, 0.f),
                                              fmaxf(d[nt][1] + bb1, 0.f));
                *(__half2*)(g_h1h + (size_t)rA * HID + n0) = h;
            }
            if (rB < N_NODES) {
                __half2 h = __floats2half2_rn(fmaxf(d[nt][2] + bb0, 0.f),
                                              fmaxf(d[nt][3] + bb1, 0.f));
                *(__half2*)(g_h1h + (size_t)rB * HID + n0) = h;
            }
        }
    }
}

// ---------------- 128-dim aggregation: gathers fp16 g_h1h, writes fp32 g_h0
// Edge loop unrolled x2 with paired gathers for higher MLP.
__global__ void k_aggregate() {
    int node = blockIdx.x * (blockDim.x >> 5) + (threadIdx.x >> 5);
    if (node >= N_NODES) return;
    int lane = threadIdx.x & 31;
    float dd = g_dis[node];
    float s0 = dd * dd;
    uint2 pv = ((const uint2*)(g_h1h + (size_t)node * HID))[lane];
    float2 v0 = __half22float2(u32_as_h2(pv.x));
    float2 v1 = __half22float2(u32_as_h2(pv.y));
    float ax = v0.x * s0, ay = v0.y * s0, az = v1.x * s0, aw = v1.y * s0;
    int beg = real_off(node), end = real_off(node + 1);
    int e = beg;
    for (; e + 2 <= end; e += 2) {
        int sa = g_srcs[e];
        int sb = g_srcs[e + 1];
        float wa = g_dis[sa] * dd;
        float wb = g_dis[sb] * dd;
        uint2 pa = ((const uint2*)(g_h1h + (size_t)sa * HID))[lane];
        uint2 pb = ((const uint2*)(g_h1h + (size_t)sb * HID))[lane];
        float2 a0 = __half22float2(u32_as_h2(pa.x));
        float2 a1 = __half22float2(u32_as_h2(pa.y));
        float2 b0 = __half22float2(u32_as_h2(pb.x));
        float2 b1 = __half22float2(u32_as_h2(pb.y));
        ax += a0.x * wa; ay += a0.y * wa; az += a1.x * wa; aw += a1.y * wa;
        ax += b0.x * wb; ay += b0.y * wb; az += b1.x * wb; aw += b1.y * wb;
    }
    if (e < end) {
        int s = g_srcs[e];
        float w = g_dis[s] * dd;
        uint2 ph = ((const uint2*)(g_h1h + (size_t)s * HID))[lane];
        float2 h0 = __half22float2(u32_as_h2(ph.x));
        float2 h1 = __half22float2(u32_as_h2(ph.y));
        ax += h0.x * w;
        ay += h0.y * w;
        az += h1.x * w;
        aw += h1.y * w;
    }
    ((float4*)(g_h0 + (size_t)node * HID))[lane] = make_float4(ax, ay, az, aw);
}

// ---------------- fused pool + fc1 + fc2 ----------------
__global__ void k_pool_fc(const float* __restrict__ fc1_w, const float* __restrict__ fc1_b,
                          const float* __restrict__ fc2_w, const float* __restrict__ fc2_b,
                          float* __restrict__ out) {
    __shared__ float pooled[HID];
    __shared__ float z[64];
    int g = blockIdx.x, c = threadIdx.x;
    int s = g_gstart[g], e = g_gstart[g + 1];
    float acc = 0.f;
    for (int i = s; i < e; i++) acc += __half2float(g_h1h[(size_t)i * HID + c]);
    float cnt = (float)((e - s) > 1 ? (e - s) : 1);
    pooled[c] = acc / cnt;
    __syncthreads();
    if (c < 64) {
        float a = fc1_b[c];
        #pragma unroll 8
        for (int k = 0; k < HID; k++) a += pooled[k] * fc1_w[k * 64 + c];
        z[c] = fmaxf(a, 0.f);
    }
    __syncthreads();
    if (c == 0) {
        float a = fc2_b[0];
        #pragma unroll 8
        for (int j = 0; j < 64; j++) a += z[j] * fc2_w[j];
        out[g] = a;
    }
}

// ---------------- launch ----------------
extern "C" void kernel_launch(void* const* d_in, const int* in_sizes, int n_in,
                              void* d_out, int out_size) {
    const float* x     = (const float*)d_in[0];
    const int*   ei    = (const int*)d_in[1];   // int64 narrowed to int32 by harness
    const int*   batch = (const int*)d_in[2];
    const float* W1 = (const float*)d_in[3];
    const float* b1 = (const float*)d_in[4];
    const float* W2 = (const float*)d_in[5];
    const float* b2 = (const float*)d_in[6];
    const float* W3 = (const float*)d_in[7];
    const float* b3 = (const float*)d_in[8];
    const float* fc1_w = (const float*)d_in[9];
    const float* fc1_b = (const float*)d_in[10];
    const float* fc2_w = (const float*)d_in[11];
    const float* fc2_b = (const float*)d_in[12];
    float* out = (float*)d_out;

    cudaFuncSetAttribute(k_gemm128_mma,
                         cudaFuncAttributeMaxDynamicSharedMemorySize, SMEM_MMA_BYTES);

    k_degree<<<(N_EDGES + 255) / 256, 256>>>(ei);
    k_scan1<<<SCAN_NB, 256>>>(batch, W2, W3);
    k_scan2<<<1, 256>>>();
    k_fill<<<(N_EDGES + 255) / 256, 256>>>(ei);

    const int AGG_BLOCKS = (N_NODES + 7) / 8;

    // layer 1 (fused agg + 6x128 gemm; tail re-zeroes counters)
    k_aggx_gemm6<<<(N_NODES + 255) / 256, 256>>>(x, W1, b1);
    // layer 2
    k_aggregate<<<AGG_BLOCKS, 256>>>();
    k_gemm128_mma<<<GEMM_CTAS, 256, SMEM_MMA_BYTES>>>(b2, 0);
    // layer 3
    k_aggregate<<<AGG_BLOCKS, 256>>>();
    k_gemm128_mma<<<GEMM_CTAS, 256, SMEM_MMA_BYTES>>>(b3, 1);

    // fused pool + MLP
    k_pool_fc<<<N_GRAPHS, HID>>>(fc1_w, fc1_b, fc2_w, fc2_b, out);
}